// round 2
// baseline (speedup 1.0000x reference)
#include <cuda_runtime.h>
#include <cuda_bf16.h>

// ---------------- problem constants ----------------
#define E_EDGES   10000
#define N_NODES_  1000
#define NC        25      // (L+1)^2
#define NRED      19
#define C_CH      128
#define C3_CH     384
#define H_CH      64
#define OUTC      128
#define WRAD_DIM  1920    // (L+1)*C3
#define X0_DIM    1088
#define YM1_DIM   512
#define YM2_DIM   384
#define MP_STRIDE (NRED*C3_CH)   // 7296 floats per edge

// ---------------- scratch (__device__ globals; no allocs) ----------------
__device__ float g_w1T [384*128];
__device__ float g_w2T [128*128];
__device__ float g_w3T [128*1920];
__device__ float g_wm0T[1920*1088];
__device__ float g_wm1T[1536*512];
__device__ float g_wm2T[1152*384];
__device__ float g_wrad[(long)E_EDGES*WRAD_DIM];
__device__ float g_mp  [(long)E_EDGES*MP_STRIDE];
__device__ float g_x0  [(long)E_EDGES*X0_DIM];
__device__ float g_ym1 [(long)E_EDGES*2*YM1_DIM];
__device__ float g_ym2 [(long)E_EDGES*2*YM2_DIM];
__device__ float g_hl  [(long)E_EDGES*NRED*H_CH];

// permutation tables
__constant__ int c_MASKP[19] = {0,2,6,12,20, 3,7,13,21, 1,5,11,19, 8,14,22, 4,10,18}; // MASK[PERM_M[j]]
__constant__ int c_MASK [19] = {0,1,2,3,4,5,6,7,8,10,11,12,13,14,18,19,20,21,22};
__constant__ int c_PERM [19] = {0,2,6,11,16, 3,7,12,17, 1,5,10,15, 8,13,18, 4,9,14};
__constant__ int c_LPERM[19] = {0,1,2,3,4, 1,2,3,4, 1,2,3,4, 2,3,4, 2,3,4};
__constant__ int c_LFULL[25] = {0,1,1,1,2,2,2,2,2,3,3,3,3,3,3,3,4,4,4,4,4,4,4,4,4};

__device__ __forceinline__ float sigm(float x){ return 1.f/(1.f+__expf(-x)); }

// ---------------- K0: transposes ----------------
__global__ void ktrans(const float* __restrict__ in, int R, int C, int which) {
    float* out;
    switch (which) {
        case 0: out = g_w1T;  break;
        case 1: out = g_w2T;  break;
        case 2: out = g_w3T;  break;
        case 3: out = g_wm0T; break;
        case 4: out = g_wm1T; break;
        default:out = g_wm2T; break;
    }
    int i = blockIdx.x*blockDim.x + threadIdx.x;
    if (i < R*C) { int r = i / C, c = i - r*C; out[c*R + r] = in[i]; }
}

// ---------------- K1: radial MLP (16 edges/block, 256 thr) ----------------
__device__ __forceinline__ void ln_silu16(float* buf, const float* __restrict__ g, const float* __restrict__ b) {
    int tid = threadIdx.x, w = tid >> 5, lane = tid & 31;
    for (int le = w; le < 16; le += 8) {
        float s = 0.f, s2 = 0.f;
        #pragma unroll
        for (int q = 0; q < 4; q++) { float v = buf[le*128 + lane + 32*q]; s += v; s2 += v*v; }
        #pragma unroll
        for (int off = 16; off > 0; off >>= 1) {
            s  += __shfl_xor_sync(0xffffffffu, s,  off);
            s2 += __shfl_xor_sync(0xffffffffu, s2, off);
        }
        float mu = s * (1.f/128.f);
        float var = s2 * (1.f/128.f) - mu*mu;
        float rstd = rsqrtf(var + 1e-5f);
        #pragma unroll
        for (int q = 0; q < 4; q++) {
            int oo = lane + 32*q;
            float v = buf[le*128 + oo];
            v = (v - mu)*rstd*g[oo] + b[oo];
            buf[le*128 + oo] = v * sigm(v);
        }
    }
}

__launch_bounds__(256)
__global__ void k1_radial(const float* __restrict__ ed,
                          const float* __restrict__ semb, const float* __restrict__ temb,
                          const float* __restrict__ b1, const float* __restrict__ g1, const float* __restrict__ bb1,
                          const float* __restrict__ b2, const float* __restrict__ g2, const float* __restrict__ bb2,
                          const float* __restrict__ b3,
                          const int* __restrict__ an, const int* __restrict__ ei) {
    __shared__ float xe[16*384];
    __shared__ float h1[16*128];
    __shared__ float h2[16*128];
    int e0 = blockIdx.x * 16;
    int tid = threadIdx.x;

    for (int idx = tid; idx < 16*384; idx += 256) {
        int le = idx / 384, c = idx - le*384;
        int e = e0 + le;
        float v;
        if (c < 128)       v = ed[e*128 + c];
        else if (c < 256)  v = semb[an[ei[e]]*128 + (c-128)];
        else               v = temb[an[ei[E_EDGES + e]]*128 + (c-256)];
        xe[idx] = v;
    }
    __syncthreads();

    int o = tid & 127, hh = tid >> 7;
    { // layer1: 384 -> 128
        float acc[8];
        float bv = b1[o];
        #pragma unroll
        for (int j = 0; j < 8; j++) acc[j] = bv;
        #pragma unroll 4
        for (int k = 0; k < 384; k++) {
            float wv = g_w1T[k*128 + o];
            #pragma unroll
            for (int j = 0; j < 8; j++) acc[j] += wv * xe[(hh*8+j)*384 + k];
        }
        #pragma unroll
        for (int j = 0; j < 8; j++) h1[(hh*8+j)*128 + o] = acc[j];
    }
    __syncthreads();
    ln_silu16(h1, g1, bb1);
    __syncthreads();
    { // layer2: 128 -> 128
        float acc[8];
        float bv = b2[o];
        #pragma unroll
        for (int j = 0; j < 8; j++) acc[j] = bv;
        #pragma unroll 4
        for (int k = 0; k < 128; k++) {
            float wv = g_w2T[k*128 + o];
            #pragma unroll
            for (int j = 0; j < 8; j++) acc[j] += wv * h1[(hh*8+j)*128 + k];
        }
        #pragma unroll
        for (int j = 0; j < 8; j++) h2[(hh*8+j)*128 + o] = acc[j];
    }
    __syncthreads();
    ln_silu16(h2, g2, bb2);
    __syncthreads();
    // layer3: 128 -> 1920
    for (int oo = tid; oo < 1920; oo += 256) {
        float acc[16];
        #pragma unroll
        for (int le = 0; le < 16; le++) acc[le] = 0.f;
        #pragma unroll 4
        for (int k = 0; k < 128; k++) {
            float wv = g_w3T[k*1920 + oo];
            #pragma unroll
            for (int le = 0; le < 16; le++) acc[le] += wv * h2[le*128 + k];
        }
        float bv = b3[oo];
        #pragma unroll
        for (int le = 0; le < 16; le++)
            g_wrad[(long)(e0+le)*1920 + oo] = acc[le] + bv;
    }
}

// ---------------- K2: msg build * w_rad, Wigner forward, permuted store ----------------
__launch_bounds__(256)
__global__ void k2_wfwd(const float* __restrict__ x, const float* __restrict__ ef,
                        const float* __restrict__ wig, const int* __restrict__ ei) {
    __shared__ float msg[25*384];
    __shared__ float wp[19*25];
    int e = blockIdx.x, tid = threadIdx.x;
    int src = ei[e], tgt = ei[E_EDGES + e];

    for (int idx = tid; idx < 19*25; idx += 256) {
        int j = idx / 25, n = idx - j*25;
        wp[idx] = wig[(long)e*625 + c_MASKP[j]*25 + n];
    }
    for (int idx = tid; idx < 25*384; idx += 256) {
        int n = idx / 384, c = idx - n*384;
        float v;
        if (c < 128)      v = x[(long)src*3200 + n*128 + c];
        else if (c < 256) v = x[(long)tgt*3200 + n*128 + (c-128)];
        else              v = ef[(long)e*3200 + n*128 + (c-256)];
        msg[idx] = v * g_wrad[(long)e*1920 + c_LFULL[n]*384 + c];
    }
    __syncthreads();

    const float4* m4 = (const float4*)msg;
    float4* out4 = (float4*)g_mp;
    for (int idx = tid; idx < 19*96; idx += 256) {
        int j = idx / 96, c4 = idx - j*96;
        float4 acc = make_float4(0.f,0.f,0.f,0.f);
        #pragma unroll
        for (int n = 0; n < 25; n++) {
            float w = wp[j*25 + n];
            float4 m = m4[n*96 + c4];
            acc.x += w*m.x; acc.y += w*m.y; acc.z += w*m.z; acc.w += w*m.w;
        }
        out4[(long)e*(MP_STRIDE/4) + idx] = acc;
    }
}

// ---------------- K3: fp32 tiled GEMM  C[M,N] = A[M,K] @ W[N,K]^T ----------------
template<int MODE>
__launch_bounds__(256)
__global__ void k3_gemm(const float* __restrict__ bias) {
    constexpr int N = (MODE==0) ? 1088 : (MODE==1) ? 512 : 384;
    constexpr int K = (MODE==0) ? 1920 : (MODE==1) ? 1536 : 1152;
    constexpr int M = (MODE==0) ? E_EDGES : 2*E_EDGES;
    const float* __restrict__ BT = (MODE==0) ? g_wm0T : (MODE==1) ? g_wm1T : g_wm2T;
    float* __restrict__ C = (MODE==0) ? g_x0 : (MODE==1) ? g_ym1 : g_ym2;

    __shared__ float As[16][128];
    __shared__ float Bs[16][64];
    int tid = threadIdx.x;
    int n0 = blockIdx.x * 64;
    int m0 = blockIdx.y * 128;
    int tx = tid & 15, ty = tid >> 4;

    float acc[8][4];
    #pragma unroll
    for (int i = 0; i < 8; i++)
        #pragma unroll
        for (int j = 0; j < 4; j++) acc[i][j] = 0.f;

    int row_l = tid >> 1, kq = tid & 1;
    int r = m0 + row_l;
    bool rvalid = (r < M);
    int rc = rvalid ? r : (M-1);
    long aoff;
    if (MODE == 0)      aoff = (long)rc * MP_STRIDE;
    else if (MODE == 1) aoff = (long)(rc>>1)*MP_STRIDE + 1920 + (long)(rc&1)*1536;
    else                aoff = (long)(rc>>1)*MP_STRIDE + 4992 + (long)(rc&1)*1152;
    const float* Ap = g_mp + aoff + kq*8;
    int kb = tid >> 4, nbq = (tid & 15)*4;

    for (int k0 = 0; k0 < K; k0 += 16) {
        float4 a0 = make_float4(0.f,0.f,0.f,0.f), a1 = a0;
        if (rvalid) {
            a0 = *(const float4*)(Ap + k0);
            a1 = *(const float4*)(Ap + k0 + 4);
        }
        float4 bv = *(const float4*)(BT + (long)(k0 + kb)*N + n0 + nbq);
        As[kq*8+0][row_l] = a0.x; As[kq*8+1][row_l] = a0.y;
        As[kq*8+2][row_l] = a0.z; As[kq*8+3][row_l] = a0.w;
        As[kq*8+4][row_l] = a1.x; As[kq*8+5][row_l] = a1.y;
        As[kq*8+6][row_l] = a1.z; As[kq*8+7][row_l] = a1.w;
        *(float4*)&Bs[kb][nbq] = bv;
        __syncthreads();
        #pragma unroll
        for (int kk = 0; kk < 16; kk++) {
            float4 av0 = *(const float4*)&As[kk][ty*8];
            float4 av1 = *(const float4*)&As[kk][ty*8+4];
            float4 bv2 = *(const float4*)&Bs[kk][tx*4];
            float a[8] = {av0.x,av0.y,av0.z,av0.w,av1.x,av1.y,av1.z,av1.w};
            float b[4] = {bv2.x,bv2.y,bv2.z,bv2.w};
            #pragma unroll
            for (int i = 0; i < 8; i++)
                #pragma unroll
                for (int j = 0; j < 4; j++) acc[i][j] += a[i]*b[j];
        }
        __syncthreads();
    }
    #pragma unroll
    for (int i = 0; i < 8; i++) {
        int r2 = m0 + ty*8 + i;
        if (r2 < M) {
            int n = n0 + tx*4;
            float4 v = make_float4(acc[i][0], acc[i][1], acc[i][2], acc[i][3]);
            if (MODE == 0) { v.x += bias[n]; v.y += bias[n+1]; v.z += bias[n+2]; v.w += bias[n+3]; }
            *(float4*)&C[(long)r2*N + n] = v;
        }
    }
}

// ---------------- K4: complex recombine + gating + inverse permutation ----------------
__launch_bounds__(128)
__global__ void k4_assemble() {
    int e = blockIdx.x, tid = threadIdx.x;
    const float* x0 = g_x0 + (long)e*X0_DIM;
    const float* y1 = g_ym1 + (long)e*1024;
    const float* y2 = g_ym2 + (long)e*768;
    float* hl = g_hl + (long)e*(NRED*H_CH);
    for (int idx = tid; idx < NRED*H_CH; idx += 128) {
        int j = idx >> 6, i = idx & 63;
        float val;
        if (j < 5)        val = x0[768 + (j<<6) + i];
        else if (j < 9)  { int jj = j-5;  val = y1[jj*64 + i]       - y1[512+256 + jj*64 + i]; }
        else if (j < 13) { int jj = j-9;  val = y1[512 + jj*64 + i] + y1[256 + jj*64 + i]; }
        else if (j < 16) { int jj = j-13; val = y2[jj*64 + i]       - y2[384+192 + jj*64 + i]; }
        else             { int jj = j-16; val = y2[384 + jj*64 + i] + y2[192 + jj*64 + i]; }
        if (j == 0) {
            val = val * sigm(val);                    // silu on l=0
        } else {
            float gsrc = x0[512 + (c_LPERM[j]-1)*64 + i];
            val *= sigm(gsrc);
        }
        hl[c_PERM[j]*64 + i] = val;
    }
}

// ---------------- K5: Wigner back + projection (2 edges/block) ----------------
__launch_bounds__(256)
__global__ void k5_out(const float* __restrict__ wig,
                       const float* __restrict__ pw, const float* __restrict__ pb,
                       float* __restrict__ out) {
    __shared__ float s_full[2*25*64];   // 3200
    __shared__ float s_buf[128*65];     // 8320 (union: wigner+hl, then proj_w[l] padded)
    int e0 = blockIdx.x * 2;
    int tid = threadIdx.x;
    float* s_w  = s_buf;        // 2*19*25 = 950
    float* s_hl = s_buf + 950;  // 2*19*64 = 2432

    for (int idx = tid; idx < 950; idx += 256) {
        int e = idx / 475, rem = idx - e*475;
        int r = rem / 25, n = rem - r*25;
        s_w[idx] = wig[(long)(e0+e)*625 + c_MASK[r]*25 + n];
    }
    for (int idx = tid; idx < 2432; idx += 256) {
        int e = idx / 1216, rem = idx - e*1216;
        s_hl[idx] = g_hl[(long)(e0+e)*1216 + rem];
    }
    __syncthreads();
    for (int idx = tid; idx < 3200; idx += 256) {
        int e = idx / 1600, rem = idx - e*1600;
        int n = rem >> 6, i = rem & 63;
        float acc = 0.f;
        #pragma unroll
        for (int r = 0; r < 19; r++)
            acc += s_w[e*475 + r*25 + n] * s_hl[e*1216 + r*64 + i];
        s_full[idx] = acc;
    }
    __syncthreads();

    int o = tid & 127, ph = tid >> 7;
    for (int l = 0; l < 5; l++) {
        __syncthreads();
        for (int idx = tid; idx < 8192; idx += 256) {
            int oo = idx >> 6, ii = idx & 63;
            s_buf[oo*65 + ii] = pw[l*8192 + idx];
        }
        __syncthreads();
        int nrows = 2*l + 1, nstart = l*l;
        int npairs = 2*nrows;
        const float* pwrow = &s_buf[o*65];
        for (int p = ph; p < npairs; p += 2) {
            int e = p & 1, nr = p >> 1;
            const float* fu = &s_full[(e*25 + nstart + nr)*64];
            float acc = 0.f;
            #pragma unroll
            for (int i0 = 0; i0 < 64; i0 += 4) {
                float4 f = *(const float4*)(fu + i0);
                acc += f.x*pwrow[i0] + f.y*pwrow[i0+1] + f.z*pwrow[i0+2] + f.w*pwrow[i0+3];
            }
            if (l == 0) acc += pb[o];
            out[(long)(e0+e)*3200 + (nstart+nr)*128 + o] = acc;
        }
    }
}

// ---------------- launch ----------------
extern "C" void kernel_launch(void* const* d_in, const int* in_sizes, int n_in,
                              void* d_out, int out_size) {
    const float* x    = (const float*)d_in[0];
    const float* ef   = (const float*)d_in[1];
    const float* ed   = (const float*)d_in[2];
    const float* wig  = (const float*)d_in[3];
    const float* semb = (const float*)d_in[4];
    const float* temb = (const float*)d_in[5];
    const float* w1   = (const float*)d_in[6];
    const float* b1   = (const float*)d_in[7];
    const float* g1   = (const float*)d_in[8];
    const float* bb1  = (const float*)d_in[9];
    const float* w2   = (const float*)d_in[10];
    const float* b2   = (const float*)d_in[11];
    const float* g2   = (const float*)d_in[12];
    const float* bb2  = (const float*)d_in[13];
    const float* w3   = (const float*)d_in[14];
    const float* b3   = (const float*)d_in[15];
    const float* wm0  = (const float*)d_in[16];
    const float* bm0  = (const float*)d_in[17];
    const float* wm1  = (const float*)d_in[18];
    const float* wm2  = (const float*)d_in[19];
    const float* pw   = (const float*)d_in[20];
    const float* pb   = (const float*)d_in[21];
    const int*   an   = (const int*)d_in[22];
    const int*   ei   = (const int*)d_in[23];
    float* out = (float*)d_out;

    // K0: weight transposes
    ktrans<<<(128*384   + 255)/256, 256>>>(w1,  128,  384,  0);
    ktrans<<<(128*128   + 255)/256, 256>>>(w2,  128,  128,  1);
    ktrans<<<(1920*128  + 255)/256, 256>>>(w3,  1920, 128,  2);
    ktrans<<<(1088*1920 + 255)/256, 256>>>(wm0, 1088, 1920, 3);
    ktrans<<<(512*1536  + 255)/256, 256>>>(wm1, 512,  1536, 4);
    ktrans<<<(384*1152  + 255)/256, 256>>>(wm2, 384,  1152, 5);

    // K1: radial MLP
    k1_radial<<<E_EDGES/16, 256>>>(ed, semb, temb, b1, g1, bb1, b2, g2, bb2, b3, an, ei);

    // K2: msg * w_rad + Wigner forward (permuted store)
    k2_wfwd<<<E_EDGES, 256>>>(x, ef, wig, ei);

    // K3: the three big GEMMs
    {
        dim3 g0(1088/64, (E_EDGES + 127)/128);
        k3_gemm<0><<<g0, 256>>>(bm0);
        dim3 g1g(512/64, (2*E_EDGES + 127)/128);
        k3_gemm<1><<<g1g, 256>>>(nullptr);
        dim3 g2g(384/64, (2*E_EDGES + 127)/128);
        k3_gemm<2><<<g2g, 256>>>(nullptr);
    }

    // K4: recombine + gate
    k4_assemble<<<E_EDGES, 128>>>();

    // K5: Wigner back + projection
    k5_out<<<E_EDGES/2, 256>>>(wig, pw, pb, out);
}

// round 4
// speedup vs baseline: 1.4535x; 1.4535x over previous
#include <cuda_runtime.h>
#include <cuda_bf16.h>
#include <cstdint>

// ---------------- problem constants ----------------
#define E_EDGES   10000
#define NRED      19
#define MP_STRIDE (NRED*384)   // 7296
#define X0_DIM    1088

// ---------------- scratch (__device__ globals) ----------------
__device__ float g_w1T [384*128];
__device__ float g_w2T [128*128];
__device__ float g_w3T [128*1920];
__device__ __nv_bfloat16 g_wm0_hi[1088*1920];
__device__ __nv_bfloat16 g_wm0_lo[1088*1920];
__device__ __nv_bfloat16 g_wm1_hi[512*1536];
__device__ __nv_bfloat16 g_wm1_lo[512*1536];
__device__ __nv_bfloat16 g_wm2_hi[384*1152];
__device__ __nv_bfloat16 g_wm2_lo[384*1152];
__device__ float g_wrad[(long)E_EDGES*1920];
__device__ __nv_bfloat16 g_mp_hi[(long)E_EDGES*MP_STRIDE];
__device__ __nv_bfloat16 g_mp_lo[(long)E_EDGES*MP_STRIDE];
__device__ float g_x0  [(long)E_EDGES*X0_DIM];
__device__ float g_ym1 [(long)E_EDGES*2*512];
__device__ float g_ym2 [(long)E_EDGES*2*384];
__device__ float g_hl  [(long)E_EDGES*NRED*64];

// permutation tables
__constant__ int c_MASKP[19] = {0,2,6,12,20, 3,7,13,21, 1,5,11,19, 8,14,22, 4,10,18};
__constant__ int c_MASK [19] = {0,1,2,3,4,5,6,7,8,10,11,12,13,14,18,19,20,21,22};
__constant__ int c_PERM [19] = {0,2,6,11,16, 3,7,12,17, 1,5,10,15, 8,13,18, 4,9,14};
__constant__ int c_LPERM[19] = {0,1,2,3,4, 1,2,3,4, 1,2,3,4, 2,3,4, 2,3,4};
__constant__ int c_LFULL[25] = {0,1,1,1,2,2,2,2,2,3,3,3,3,3,3,3,4,4,4,4,4,4,4,4,4};

__device__ __forceinline__ float sigm(float x){ return 1.f/(1.f+__expf(-x)); }

__device__ __forceinline__ uint32_t smem_u32(const void* p) {
    uint32_t a;
    asm("{ .reg .u64 t; cvta.to.shared.u64 t, %1; cvt.u32.u64 %0, t; }" : "=r"(a) : "l"(p));
    return a;
}
__device__ __forceinline__ void cp16(uint32_t dst, const void* src) {
    asm volatile("cp.async.cg.shared.global [%0], [%1], 16;" :: "r"(dst), "l"(src));
}
__device__ __forceinline__ void ldm_x4(uint32_t addr, uint32_t* r) {
    asm volatile("ldmatrix.sync.aligned.m8n8.x4.shared.b16 {%0,%1,%2,%3}, [%4];"
                 : "=r"(r[0]), "=r"(r[1]), "=r"(r[2]), "=r"(r[3]) : "r"(addr));
}
__device__ __forceinline__ void mma16816(float* d, const uint32_t* a, uint32_t b0, uint32_t b1) {
    asm volatile("mma.sync.aligned.m16n8k16.row.col.f32.bf16.bf16.f32 "
                 "{%0,%1,%2,%3}, {%4,%5,%6,%7}, {%8,%9}, {%0,%1,%2,%3};"
                 : "+f"(d[0]), "+f"(d[1]), "+f"(d[2]), "+f"(d[3])
                 : "r"(a[0]), "r"(a[1]), "r"(a[2]), "r"(a[3]), "r"(b0), "r"(b1));
}

// ---------------- K0a: small transposes for radial MLP ----------------
__global__ void ktrans(const float* __restrict__ in, int R, int C, int which) {
    float* out = (which == 0) ? g_w1T : (which == 1) ? g_w2T : g_w3T;
    int i = blockIdx.x*blockDim.x + threadIdx.x;
    if (i < R*C) { int r = i / C, c = i - r*C; out[c*R + r] = in[i]; }
}

// ---------------- K0b: weight fp32 -> (hi,lo) bf16 split ----------------
__global__ void kconv(const float* __restrict__ in, int n, int which) {
    __nv_bfloat16 *hi, *lo;
    if (which == 0)      { hi = g_wm0_hi; lo = g_wm0_lo; }
    else if (which == 1) { hi = g_wm1_hi; lo = g_wm1_lo; }
    else                 { hi = g_wm2_hi; lo = g_wm2_lo; }
    int i = blockIdx.x*blockDim.x + threadIdx.x;
    if (i < n) {
        float v = in[i];
        __nv_bfloat16 h = __float2bfloat16(v);
        hi[i] = h;
        lo[i] = __float2bfloat16(v - __bfloat162float(h));
    }
}

// ---------------- K1: radial MLP (16 edges/block) ----------------
__device__ __forceinline__ void ln_silu16(float* buf, const float* __restrict__ g, const float* __restrict__ b) {
    int tid = threadIdx.x, w = tid >> 5, lane = tid & 31;
    for (int le = w; le < 16; le += 8) {
        float s = 0.f, s2 = 0.f;
        #pragma unroll
        for (int q = 0; q < 4; q++) { float v = buf[le*128 + lane + 32*q]; s += v; s2 += v*v; }
        #pragma unroll
        for (int off = 16; off > 0; off >>= 1) {
            s  += __shfl_xor_sync(0xffffffffu, s,  off);
            s2 += __shfl_xor_sync(0xffffffffu, s2, off);
        }
        float mu = s * (1.f/128.f);
        float var = s2 * (1.f/128.f) - mu*mu;
        float rstd = rsqrtf(var + 1e-5f);
        #pragma unroll
        for (int q = 0; q < 4; q++) {
            int oo = lane + 32*q;
            float v = buf[le*128 + oo];
            v = (v - mu)*rstd*g[oo] + b[oo];
            buf[le*128 + oo] = v * sigm(v);
        }
    }
}

__launch_bounds__(256)
__global__ void k1_radial(const float* __restrict__ ed,
                          const float* __restrict__ semb, const float* __restrict__ temb,
                          const float* __restrict__ b1, const float* __restrict__ g1, const float* __restrict__ bb1,
                          const float* __restrict__ b2, const float* __restrict__ g2, const float* __restrict__ bb2,
                          const float* __restrict__ b3,
                          const int* __restrict__ an, const int* __restrict__ ei) {
    __shared__ float xe[16*384];
    __shared__ float h1[16*128];
    __shared__ float h2[16*128];
    int e0 = blockIdx.x * 16;
    int tid = threadIdx.x;

    for (int idx = tid; idx < 16*384; idx += 256) {
        int le = idx / 384, c = idx - le*384;
        int e = e0 + le;
        float v;
        if (c < 128)       v = ed[e*128 + c];
        else if (c < 256)  v = semb[an[ei[e]]*128 + (c-128)];
        else               v = temb[an[ei[E_EDGES + e]]*128 + (c-256)];
        xe[idx] = v;
    }
    __syncthreads();

    int o = tid & 127, hh = tid >> 7;
    {
        float acc[8]; float bv = b1[o];
        #pragma unroll
        for (int j = 0; j < 8; j++) acc[j] = bv;
        #pragma unroll 4
        for (int k = 0; k < 384; k++) {
            float wv = g_w1T[k*128 + o];
            #pragma unroll
            for (int j = 0; j < 8; j++) acc[j] += wv * xe[(hh*8+j)*384 + k];
        }
        #pragma unroll
        for (int j = 0; j < 8; j++) h1[(hh*8+j)*128 + o] = acc[j];
    }
    __syncthreads();
    ln_silu16(h1, g1, bb1);
    __syncthreads();
    {
        float acc[8]; float bv = b2[o];
        #pragma unroll
        for (int j = 0; j < 8; j++) acc[j] = bv;
        #pragma unroll 4
        for (int k = 0; k < 128; k++) {
            float wv = g_w2T[k*128 + o];
            #pragma unroll
            for (int j = 0; j < 8; j++) acc[j] += wv * h1[(hh*8+j)*128 + k];
        }
        #pragma unroll
        for (int j = 0; j < 8; j++) h2[(hh*8+j)*128 + o] = acc[j];
    }
    __syncthreads();
    ln_silu16(h2, g2, bb2);
    __syncthreads();
    for (int oo = tid; oo < 1920; oo += 256) {
        float acc[16];
        #pragma unroll
        for (int le = 0; le < 16; le++) acc[le] = 0.f;
        #pragma unroll 4
        for (int k = 0; k < 128; k++) {
            float wv = g_w3T[k*1920 + oo];
            #pragma unroll
            for (int le = 0; le < 16; le++) acc[le] += wv * h2[le*128 + k];
        }
        float bv = b3[oo];
        #pragma unroll
        for (int le = 0; le < 16; le++)
            g_wrad[(long)(e0+le)*1920 + oo] = acc[le] + bv;
    }
}

// ---------------- K2: msg build * w_rad, Wigner fwd, permuted bf16-split store ----------------
__launch_bounds__(256)
__global__ void k2_wfwd(const float* __restrict__ x, const float* __restrict__ ef,
                        const float* __restrict__ wig, const int* __restrict__ ei) {
    __shared__ float msg[25*384];
    __shared__ float wp[19*25];
    int e = blockIdx.x, tid = threadIdx.x;
    int src = ei[e], tgt = ei[E_EDGES + e];

    for (int idx = tid; idx < 19*25; idx += 256) {
        int j = idx / 25, n = idx - j*25;
        wp[idx] = wig[(long)e*625 + c_MASKP[j]*25 + n];
    }
    for (int idx = tid; idx < 25*384; idx += 256) {
        int n = idx / 384, c = idx - n*384;
        float v;
        if (c < 128)      v = x[(long)src*3200 + n*128 + c];
        else if (c < 256) v = x[(long)tgt*3200 + n*128 + (c-128)];
        else              v = ef[(long)e*3200 + n*128 + (c-256)];
        msg[idx] = v * g_wrad[(long)e*1920 + c_LFULL[n]*384 + c];
    }
    __syncthreads();

    const float4* m4 = (const float4*)msg;
    for (int idx = tid; idx < 19*96; idx += 256) {
        float4 acc = make_float4(0.f,0.f,0.f,0.f);
        int j = idx / 96, c4 = idx - j*96;
        #pragma unroll
        for (int n = 0; n < 25; n++) {
            float w = wp[j*25 + n];
            float4 m = m4[n*96 + c4];
            acc.x += w*m.x; acc.y += w*m.y; acc.z += w*m.z; acc.w += w*m.w;
        }
        long base = (long)e*MP_STRIDE + (long)idx*4;
        __nv_bfloat16 h0 = __float2bfloat16(acc.x);
        __nv_bfloat16 h1 = __float2bfloat16(acc.y);
        __nv_bfloat16 h2 = __float2bfloat16(acc.z);
        __nv_bfloat16 h3 = __float2bfloat16(acc.w);
        __nv_bfloat162 hp0; hp0.x = h0; hp0.y = h1;
        __nv_bfloat162 hp1; hp1.x = h2; hp1.y = h3;
        ((__nv_bfloat162*)(g_mp_hi + base))[0] = hp0;
        ((__nv_bfloat162*)(g_mp_hi + base))[1] = hp1;
        __nv_bfloat162 lp0, lp1;
        lp0.x = __float2bfloat16(acc.x - __bfloat162float(h0));
        lp0.y = __float2bfloat16(acc.y - __bfloat162float(h1));
        lp1.x = __float2bfloat16(acc.z - __bfloat162float(h2));
        lp1.y = __float2bfloat16(acc.w - __bfloat162float(h3));
        ((__nv_bfloat162*)(g_mp_lo + base))[0] = lp0;
        ((__nv_bfloat162*)(g_mp_lo + base))[1] = lp1;
    }
}

// ---------------- K3: mma.sync bf16x3 GEMM  C[M,N] = A[M,K] @ W[N,K]^T ----------------
// CTA 128x128, 8 warps (2 M x 4 N), warp tile 64x32, K-chunk 32, 3-stage cp.async.
// 3 passes over K: (Ahi,Whi), (Ahi,Wlo), (Alo,Whi); fp32 register accumulators.
#define K3_ROWB    80        // padded row stride in bytes (32 bf16 + 8 pad)
#define K3_ASZ     (128*K3_ROWB)   // 10240
#define K3_STG     (2*K3_ASZ)      // 20480 per stage
#define K3_DSMEM   (3*K3_STG)      // 61440

template<int MODE>
__launch_bounds__(256, 2)
__global__ void k3_mma(const float* __restrict__ bias) {
    constexpr int N  = (MODE==0) ? 1088 : (MODE==1) ? 512 : 384;
    constexpr int K  = (MODE==0) ? 1920 : (MODE==1) ? 1536 : 1152;
    constexpr int M  = (MODE==0) ? E_EDGES : 2*E_EDGES;
    constexpr int KC  = K / 32;
    constexpr int NCH = 3 * KC;
    const __nv_bfloat16* __restrict__ Whi = (MODE==0) ? g_wm0_hi : (MODE==1) ? g_wm1_hi : g_wm2_hi;
    const __nv_bfloat16* __restrict__ Wlo = (MODE==0) ? g_wm0_lo : (MODE==1) ? g_wm1_lo : g_wm2_lo;
    float* __restrict__ C = (MODE==0) ? g_x0 : (MODE==1) ? g_ym1 : g_ym2;

    extern __shared__ char dsm[];
    const uint32_t smb = smem_u32(dsm);
    const int tid = threadIdx.x;
    const int wid = tid >> 5, lane = tid & 31;
    const int n0 = blockIdx.x * 128;
    const int m0 = blockIdx.y * 128;
    const int wm = (wid & 1) * 64;     // warp M offset in tile
    const int wn = (wid >> 1) * 32;    // warp N offset in tile

    float acc[4][4][4];
    #pragma unroll
    for (int i = 0; i < 4; i++)
        #pragma unroll
        for (int j = 0; j < 4; j++)
            #pragma unroll
            for (int q = 0; q < 4; q++) acc[i][j][q] = 0.f;

    // precompute this thread's two A-row / B-row load slots
    int u0 = tid, u1 = tid + 256;
    int ar0 = u0 >> 2, aq0 = (u0 & 3), ar1 = u1 >> 2, aq1 = (u1 & 3);
    long abase0, abase1;
    {
        int r0 = m0 + ar0; if (r0 >= M) r0 = 0;
        int r1 = m0 + ar1; if (r1 >= M) r1 = 0;
        if (MODE == 0)      { abase0 = (long)r0*MP_STRIDE;                              abase1 = (long)r1*MP_STRIDE; }
        else if (MODE == 1) { abase0 = (long)(r0>>1)*MP_STRIDE + 1920 + (long)(r0&1)*1536; abase1 = (long)(r1>>1)*MP_STRIDE + 1920 + (long)(r1&1)*1536; }
        else                { abase0 = (long)(r0>>1)*MP_STRIDE + 4992 + (long)(r0&1)*1152; abase1 = (long)(r1>>1)*MP_STRIDE + 4992 + (long)(r1&1)*1152; }
    }
    long bbase0, bbase1;
    {
        int n_0 = n0 + ar0; if (n_0 >= N) n_0 = N-1;
        int n_1 = n0 + ar1; if (n_1 >= N) n_1 = N-1;
        bbase0 = (long)n_0 * K; bbase1 = (long)n_1 * K;
    }

    auto issue = [&](int c, int stage) {
        if (c < NCH) {
            int pass = c / KC, kc = c - pass*KC, k0 = kc*32;
            const __nv_bfloat16* Asrc = (pass < 2) ? g_mp_hi : g_mp_lo;
            const __nv_bfloat16* Bsrc = (pass == 1) ? Wlo : Whi;
            uint32_t sA = smb + stage*K3_STG;
            uint32_t sB = sA + K3_ASZ;
            cp16(sA + ar0*K3_ROWB + aq0*16, Asrc + abase0 + k0 + aq0*8);
            cp16(sA + ar1*K3_ROWB + aq1*16, Asrc + abase1 + k0 + aq1*8);
            cp16(sB + ar0*K3_ROWB + aq0*16, Bsrc + bbase0 + k0 + aq0*8);
            cp16(sB + ar1*K3_ROWB + aq1*16, Bsrc + bbase1 + k0 + aq1*8);
        }
        asm volatile("cp.async.commit_group;" ::: "memory");
    };

    issue(0, 0); issue(1, 1); issue(2, 2);

    // ldmatrix lane addressing
    const int a_row = lane & 15, a_kh = lane >> 4;
    const int b_nl  = (lane & 7) | ((lane >> 4) << 3);
    const int b_kh  = (lane >> 3) & 1;

    for (int c = 0; c < NCH; c++) {
        int stage = c % 3;
        asm volatile("cp.async.wait_group 2;" ::: "memory");
        __syncthreads();
        uint32_t sA = smb + stage*K3_STG;
        uint32_t sB = sA + K3_ASZ;
        #pragma unroll
        for (int ks = 0; ks < 2; ks++) {
            uint32_t af[4][4];
            uint32_t aaddr = sA + (wm + a_row)*K3_ROWB + a_kh*16 + ks*32;
            #pragma unroll
            for (int mi = 0; mi < 4; mi++)
                ldm_x4(aaddr + mi*16*K3_ROWB, af[mi]);
            uint32_t bf[2][4];
            uint32_t baddr = sB + (wn + b_nl)*K3_ROWB + b_kh*16 + ks*32;
            ldm_x4(baddr, bf[0]);
            ldm_x4(baddr + 16*K3_ROWB, bf[1]);
            #pragma unroll
            for (int mi = 0; mi < 4; mi++)
                #pragma unroll
                for (int ni = 0; ni < 4; ni++)
                    mma16816(acc[mi][ni], af[mi], bf[ni>>1][(ni&1)*2], bf[ni>>1][(ni&1)*2+1]);
        }
        __syncthreads();
        issue(c + 3, stage);
    }

    // epilogue
    int tg = lane >> 2, tig = lane & 3;
    #pragma unroll
    for (int mi = 0; mi < 4; mi++) {
        #pragma unroll
        for (int ni = 0; ni < 4; ni++) {
            int row = m0 + wm + 16*mi + tg;
            int col = n0 + wn + 8*ni + 2*tig;
            if (col < N) {
                float bx = 0.f, by = 0.f;
                if (MODE == 0) { bx = bias[col]; by = bias[col+1]; }
                if (row < M) {
                    float2 v = make_float2(acc[mi][ni][0] + bx, acc[mi][ni][1] + by);
                    *(float2*)(C + (long)row*N + col) = v;
                }
                if (row + 8 < M) {
                    float2 v = make_float2(acc[mi][ni][2] + bx, acc[mi][ni][3] + by);
                    *(float2*)(C + (long)(row+8)*N + col) = v;
                }
            }
        }
    }
}

// ---------------- K4: complex recombine + gating + inverse permutation ----------------
__launch_bounds__(128)
__global__ void k4_assemble() {
    int e = blockIdx.x, tid = threadIdx.x;
    const float* x0 = g_x0 + (long)e*X0_DIM;
    const float* y1 = g_ym1 + (long)e*1024;
    const float* y2 = g_ym2 + (long)e*768;
    float* hl = g_hl + (long)e*(NRED*64);
    for (int idx = tid; idx < NRED*64; idx += 128) {
        int j = idx >> 6, i = idx & 63;
        float val;
        if (j < 5)        val = x0[768 + (j<<6) + i];
        else if (j < 9)  { int jj = j-5;  val = y1[jj*64 + i]       - y1[512+256 + jj*64 + i]; }
        else if (j < 13) { int jj = j-9;  val = y1[512 + jj*64 + i] + y1[256 + jj*64 + i]; }
        else if (j < 16) { int jj = j-13; val = y2[jj*64 + i]       - y2[384+192 + jj*64 + i]; }
        else             { int jj = j-16; val = y2[384 + jj*64 + i] + y2[192 + jj*64 + i]; }
        if (j == 0) {
            val = val * sigm(val);
        } else {
            float gsrc = x0[512 + (c_LPERM[j]-1)*64 + i];
            val *= sigm(gsrc);
        }
        hl[c_PERM[j]*64 + i] = val;
    }
}

// ---------------- K5: Wigner back + projection (2 edges/block) ----------------
__launch_bounds__(256)
__global__ void k5_out(const float* __restrict__ wig,
                       const float* __restrict__ pw, const float* __restrict__ pb,
                       float* __restrict__ out) {
    __shared__ float s_full[2*25*64];
    __shared__ float s_buf[128*65];
    int e0 = blockIdx.x * 2;
    int tid = threadIdx.x;
    float* s_w  = s_buf;
    float* s_hl = s_buf + 950;

    for (int idx = tid; idx < 950; idx += 256) {
        int e = idx / 475, rem = idx - e*475;
        int r = rem / 25, n = rem - r*25;
        s_w[idx] = wig[(long)(e0+e)*625 + c_MASK[r]*25 + n];
    }
    for (int idx = tid; idx < 2432; idx += 256) {
        int e = idx / 1216, rem = idx - e*1216;
        s_hl[idx] = g_hl[(long)(e0+e)*1216 + rem];
    }
    __syncthreads();
    for (int idx = tid; idx < 3200; idx += 256) {
        int e = idx / 1600, rem = idx - e*1600;
        int n = rem >> 6, i = rem & 63;
        float acc = 0.f;
        #pragma unroll
        for (int r = 0; r < 19; r++)
            acc += s_w[e*475 + r*25 + n] * s_hl[e*1216 + r*64 + i];
        s_full[idx] = acc;
    }
    __syncthreads();

    int o = tid & 127, ph = tid >> 7;
    for (int l = 0; l < 5; l++) {
        __syncthreads();
        for (int idx = tid; idx < 8192; idx += 256) {
            int oo = idx >> 6, ii = idx & 63;
            s_buf[oo*65 + ii] = pw[l*8192 + idx];
        }
        __syncthreads();
        int nrows = 2*l + 1, nstart = l*l;
        int npairs = 2*nrows;
        const float* pwrow = &s_buf[o*65];
        for (int p = ph; p < npairs; p += 2) {
            int e = p & 1, nr = p >> 1;
            const float* fu = &s_full[(e*25 + nstart + nr)*64];
            float acc = 0.f;
            #pragma unroll
            for (int i0 = 0; i0 < 64; i0 += 4) {
                float4 f = *(const float4*)(fu + i0);
                acc += f.x*pwrow[i0] + f.y*pwrow[i0+1] + f.z*pwrow[i0+2] + f.w*pwrow[i0+3];
            }
            if (l == 0) acc += pb[o];
            out[(long)(e0+e)*3200 + (nstart+nr)*128 + o] = acc;
        }
    }
}

// ---------------- launch ----------------
extern "C" void kernel_launch(void* const* d_in, const int* in_sizes, int n_in,
                              void* d_out, int out_size) {
    const float* x    = (const float*)d_in[0];
    const float* ef   = (const float*)d_in[1];
    const float* ed   = (const float*)d_in[2];
    const float* wig  = (const float*)d_in[3];
    const float* semb = (const float*)d_in[4];
    const float* temb = (const float*)d_in[5];
    const float* w1   = (const float*)d_in[6];
    const float* b1   = (const float*)d_in[7];
    const float* g1   = (const float*)d_in[8];
    const float* bb1  = (const float*)d_in[9];
    const float* w2   = (const float*)d_in[10];
    const float* b2   = (const float*)d_in[11];
    const float* g2   = (const float*)d_in[12];
    const float* bb2  = (const float*)d_in[13];
    const float* w3   = (const float*)d_in[14];
    const float* b3   = (const float*)d_in[15];
    const float* wm0  = (const float*)d_in[16];
    const float* bm0  = (const float*)d_in[17];
    const float* wm1  = (const float*)d_in[18];
    const float* wm2  = (const float*)d_in[19];
    const float* pw   = (const float*)d_in[20];
    const float* pb   = (const float*)d_in[21];
    const int*   an   = (const int*)d_in[22];
    const int*   ei   = (const int*)d_in[23];
    float* out = (float*)d_out;

    static bool attr_done = false;
    if (!attr_done) {
        cudaFuncSetAttribute(k3_mma<0>, cudaFuncAttributeMaxDynamicSharedMemorySize, K3_DSMEM);
        cudaFuncSetAttribute(k3_mma<1>, cudaFuncAttributeMaxDynamicSharedMemorySize, K3_DSMEM);
        cudaFuncSetAttribute(k3_mma<2>, cudaFuncAttributeMaxDynamicSharedMemorySize, K3_DSMEM);
        attr_done = true;
    }

    // K0: small transposes + weight bf16 splits
    ktrans<<<(128*384  + 255)/256, 256>>>(w1, 128,  384, 0);
    ktrans<<<(128*128  + 255)/256, 256>>>(w2, 128,  128, 1);
    ktrans<<<(1920*128 + 255)/256, 256>>>(w3, 1920, 128, 2);
    kconv<<<(1088*1920 + 255)/256, 256>>>(wm0, 1088*1920, 0);
    kconv<<<(512*1536  + 255)/256, 256>>>(wm1, 512*1536,  1);
    kconv<<<(384*1152  + 255)/256, 256>>>(wm2, 384*1152,  2);

    // K1: radial MLP
    k1_radial<<<E_EDGES/16, 256>>>(ed, semb, temb, b1, g1, bb1, b2, g2, bb2, b3, an, ei);

    // K2: msg * w_rad + Wigner forward (permuted, bf16-split store)
    k2_wfwd<<<E_EDGES, 256>>>(x, ef, wig, ei);

    // K3: tensor-core (mma.sync) GEMMs
    k3_mma<0><<<dim3(9, 79),  256, K3_DSMEM>>>(bm0);
    k3_mma<1><<<dim3(4, 157), 256, K3_DSMEM>>>(nullptr);
    k3_mma<2><<<dim3(3, 157), 256, K3_DSMEM>>>(nullptr);

    // K4: recombine + gate
    k4_assemble<<<E_EDGES, 128>>>();

    // K5: Wigner back + projection
    k5_out<<<E_EDGES/2, 256>>>(wig, pw, pb, out);
}

// round 5
// speedup vs baseline: 1.5257x; 1.0497x over previous
#include <cuda_runtime.h>
#include <cuda_bf16.h>
#include <cstdint>

// ---------------- problem constants ----------------
#define E_EDGES   10000
#define NRED      19
#define MP_STRIDE (NRED*384)   // 7296
#define X0_DIM    1088

// ---------------- scratch (__device__ globals) ----------------
__device__ float g_w1T [384*128];
__device__ float g_w2T [128*128];
__device__ float g_w3T [128*1920];
__device__ __nv_bfloat16 g_wm0_hi[1088*1920];
__device__ __nv_bfloat16 g_wm0_lo[1088*1920];
__device__ __nv_bfloat16 g_wm1_hi[512*1536];
__device__ __nv_bfloat16 g_wm1_lo[512*1536];
__device__ __nv_bfloat16 g_wm2_hi[384*1152];
__device__ __nv_bfloat16 g_wm2_lo[384*1152];
__device__ float g_wrad[(long)E_EDGES*1920];
__device__ __nv_bfloat16 g_mp_hi[(long)E_EDGES*MP_STRIDE];
__device__ __nv_bfloat16 g_mp_lo[(long)E_EDGES*MP_STRIDE];
__device__ float g_x0  [(long)E_EDGES*X0_DIM];
__device__ float g_ym1 [(long)E_EDGES*2*512];
__device__ float g_ym2 [(long)E_EDGES*2*384];

// permutation tables
__constant__ int c_MASKP[19] = {0,2,6,12,20, 3,7,13,21, 1,5,11,19, 8,14,22, 4,10,18};
__constant__ int c_MASK [19] = {0,1,2,3,4,5,6,7,8,10,11,12,13,14,18,19,20,21,22};
__constant__ int c_PERM [19] = {0,2,6,11,16, 3,7,12,17, 1,5,10,15, 8,13,18, 4,9,14};
__constant__ int c_LPERM[19] = {0,1,2,3,4, 1,2,3,4, 1,2,3,4, 2,3,4, 2,3,4};
__constant__ int c_LFULL[25] = {0,1,1,1,2,2,2,2,2,3,3,3,3,3,3,3,4,4,4,4,4,4,4,4,4};

__device__ __forceinline__ float sigm(float x){ return 1.f/(1.f+__expf(-x)); }

__device__ __forceinline__ uint32_t smem_u32(const void* p) {
    uint32_t a;
    asm("{ .reg .u64 t; cvta.to.shared.u64 t, %1; cvt.u32.u64 %0, t; }" : "=r"(a) : "l"(p));
    return a;
}
__device__ __forceinline__ void cp16(uint32_t dst, const void* src) {
    asm volatile("cp.async.cg.shared.global [%0], [%1], 16;" :: "r"(dst), "l"(src));
}
__device__ __forceinline__ void ldm_x4(uint32_t addr, uint32_t* r) {
    asm volatile("ldmatrix.sync.aligned.m8n8.x4.shared.b16 {%0,%1,%2,%3}, [%4];"
                 : "=r"(r[0]), "=r"(r[1]), "=r"(r[2]), "=r"(r[3]) : "r"(addr));
}
__device__ __forceinline__ void mma16816(float* d, const uint32_t* a, uint32_t b0, uint32_t b1) {
    asm volatile("mma.sync.aligned.m16n8k16.row.col.f32.bf16.bf16.f32 "
                 "{%0,%1,%2,%3}, {%4,%5,%6,%7}, {%8,%9}, {%0,%1,%2,%3};"
                 : "+f"(d[0]), "+f"(d[1]), "+f"(d[2]), "+f"(d[3])
                 : "r"(a[0]), "r"(a[1]), "r"(a[2]), "r"(a[3]), "r"(b0), "r"(b1));
}

// ---------------- K0a: small transposes for radial MLP ----------------
__global__ void ktrans(const float* __restrict__ in, int R, int C, int which) {
    float* out = (which == 0) ? g_w1T : (which == 1) ? g_w2T : g_w3T;
    int i = blockIdx.x*blockDim.x + threadIdx.x;
    if (i < R*C) { int r = i / C, c = i - r*C; out[c*R + r] = in[i]; }
}

// ---------------- K0b: weight fp32 -> (hi,lo) bf16 split ----------------
__global__ void kconv(const float* __restrict__ in, int n, int which) {
    __nv_bfloat16 *hi, *lo;
    if (which == 0)      { hi = g_wm0_hi; lo = g_wm0_lo; }
    else if (which == 1) { hi = g_wm1_hi; lo = g_wm1_lo; }
    else                 { hi = g_wm2_hi; lo = g_wm2_lo; }
    int i = blockIdx.x*blockDim.x + threadIdx.x;
    if (i < n) {
        float v = in[i];
        __nv_bfloat16 h = __float2bfloat16(v);
        hi[i] = h;
        lo[i] = __float2bfloat16(v - __bfloat162float(h));
    }
}

// ---------------- K1: radial MLP (16 edges/block) ----------------
__device__ __forceinline__ void ln_silu16(float* buf, const float* __restrict__ g, const float* __restrict__ b) {
    int tid = threadIdx.x, w = tid >> 5, lane = tid & 31;
    for (int le = w; le < 16; le += 8) {
        float s = 0.f, s2 = 0.f;
        #pragma unroll
        for (int q = 0; q < 4; q++) { float v = buf[le*128 + lane + 32*q]; s += v; s2 += v*v; }
        #pragma unroll
        for (int off = 16; off > 0; off >>= 1) {
            s  += __shfl_xor_sync(0xffffffffu, s,  off);
            s2 += __shfl_xor_sync(0xffffffffu, s2, off);
        }
        float mu = s * (1.f/128.f);
        float var = s2 * (1.f/128.f) - mu*mu;
        float rstd = rsqrtf(var + 1e-5f);
        #pragma unroll
        for (int q = 0; q < 4; q++) {
            int oo = lane + 32*q;
            float v = buf[le*128 + oo];
            v = (v - mu)*rstd*g[oo] + b[oo];
            buf[le*128 + oo] = v * sigm(v);
        }
    }
}

__launch_bounds__(256)
__global__ void k1_radial(const float* __restrict__ ed,
                          const float* __restrict__ semb, const float* __restrict__ temb,
                          const float* __restrict__ b1, const float* __restrict__ g1, const float* __restrict__ bb1,
                          const float* __restrict__ b2, const float* __restrict__ g2, const float* __restrict__ bb2,
                          const float* __restrict__ b3,
                          const int* __restrict__ an, const int* __restrict__ ei) {
    __shared__ float xe[16*384];
    __shared__ float h1[16*128];
    __shared__ float h2[16*128];
    int e0 = blockIdx.x * 16;
    int tid = threadIdx.x;

    for (int idx = tid; idx < 16*384; idx += 256) {
        int le = idx / 384, c = idx - le*384;
        int e = e0 + le;
        float v;
        if (c < 128)       v = ed[e*128 + c];
        else if (c < 256)  v = semb[an[ei[e]]*128 + (c-128)];
        else               v = temb[an[ei[E_EDGES + e]]*128 + (c-256)];
        xe[idx] = v;
    }
    __syncthreads();

    int o = tid & 127, hh = tid >> 7;
    {
        float acc[8]; float bv = b1[o];
        #pragma unroll
        for (int j = 0; j < 8; j++) acc[j] = bv;
        #pragma unroll 4
        for (int k = 0; k < 384; k++) {
            float wv = g_w1T[k*128 + o];
            #pragma unroll
            for (int j = 0; j < 8; j++) acc[j] += wv * xe[(hh*8+j)*384 + k];
        }
        #pragma unroll
        for (int j = 0; j < 8; j++) h1[(hh*8+j)*128 + o] = acc[j];
    }
    __syncthreads();
    ln_silu16(h1, g1, bb1);
    __syncthreads();
    {
        float acc[8]; float bv = b2[o];
        #pragma unroll
        for (int j = 0; j < 8; j++) acc[j] = bv;
        #pragma unroll 4
        for (int k = 0; k < 128; k++) {
            float wv = g_w2T[k*128 + o];
            #pragma unroll
            for (int j = 0; j < 8; j++) acc[j] += wv * h1[(hh*8+j)*128 + k];
        }
        #pragma unroll
        for (int j = 0; j < 8; j++) h2[(hh*8+j)*128 + o] = acc[j];
    }
    __syncthreads();
    ln_silu16(h2, g2, bb2);
    __syncthreads();
    for (int oo = tid; oo < 1920; oo += 256) {
        float acc[16];
        #pragma unroll
        for (int le = 0; le < 16; le++) acc[le] = 0.f;
        #pragma unroll 4
        for (int k = 0; k < 128; k++) {
            float wv = g_w3T[k*1920 + oo];
            #pragma unroll
            for (int le = 0; le < 16; le++) acc[le] += wv * h2[le*128 + k];
        }
        float bv = b3[oo];
        #pragma unroll
        for (int le = 0; le < 16; le++)
            g_wrad[(long)(e0+le)*1920 + oo] = acc[le] + bv;
    }
}

// ---------------- K2: msg build * w_rad, Wigner fwd, permuted bf16-split store ----------------
__launch_bounds__(256)
__global__ void k2_wfwd(const float* __restrict__ x, const float* __restrict__ ef,
                        const float* __restrict__ wig, const int* __restrict__ ei) {
    __shared__ float msg[25*384];
    __shared__ float wp[19*25];
    int e = blockIdx.x, tid = threadIdx.x;
    int src = ei[e], tgt = ei[E_EDGES + e];

    for (int idx = tid; idx < 475; idx += 256) {
        int j = idx / 25, n = idx - j*25;
        wp[idx] = wig[(long)e*625 + c_MASKP[j]*25 + n];
    }
    const float4* x4  = (const float4*)x;
    const float4* ef4 = (const float4*)ef;
    const float4* wr4 = (const float4*)(g_wrad + (long)e*1920);
    float4* msg4 = (float4*)msg;
    for (int idx = tid; idx < 25*96; idx += 256) {
        int n = idx / 96, c4 = idx - n*96;
        float4 v;
        if (c4 < 32)      v = x4[(long)src*800 + n*32 + c4];
        else if (c4 < 64) v = x4[(long)tgt*800 + n*32 + (c4-32)];
        else              v = ef4[(long)e*800 + n*32 + (c4-64)];
        float4 w = wr4[c_LFULL[n]*96 + c4];
        v.x *= w.x; v.y *= w.y; v.z *= w.z; v.w *= w.w;
        msg4[idx] = v;
    }
    __syncthreads();

    const float4* m4 = (const float4*)msg;
    for (int idx = tid; idx < 19*96; idx += 256) {
        float4 acc = make_float4(0.f,0.f,0.f,0.f);
        int j = idx / 96, c4 = idx - j*96;
        #pragma unroll
        for (int n = 0; n < 25; n++) {
            float w = wp[j*25 + n];
            float4 m = m4[n*96 + c4];
            acc.x += w*m.x; acc.y += w*m.y; acc.z += w*m.z; acc.w += w*m.w;
        }
        long base = (long)e*MP_STRIDE + (long)idx*4;
        __nv_bfloat16 h0 = __float2bfloat16(acc.x);
        __nv_bfloat16 h1 = __float2bfloat16(acc.y);
        __nv_bfloat16 h2 = __float2bfloat16(acc.z);
        __nv_bfloat16 h3 = __float2bfloat16(acc.w);
        __nv_bfloat162 hp0; hp0.x = h0; hp0.y = h1;
        __nv_bfloat162 hp1; hp1.x = h2; hp1.y = h3;
        ((__nv_bfloat162*)(g_mp_hi + base))[0] = hp0;
        ((__nv_bfloat162*)(g_mp_hi + base))[1] = hp1;
        __nv_bfloat162 lp0, lp1;
        lp0.x = __float2bfloat16(acc.x - __bfloat162float(h0));
        lp0.y = __float2bfloat16(acc.y - __bfloat162float(h1));
        lp1.x = __float2bfloat16(acc.z - __bfloat162float(h2));
        lp1.y = __float2bfloat16(acc.w - __bfloat162float(h3));
        ((__nv_bfloat162*)(g_mp_lo + base))[0] = lp0;
        ((__nv_bfloat162*)(g_mp_lo + base))[1] = lp1;
    }
}

// ---------------- K3: mma.sync bf16x3 GEMM, CTA 128x256, hi/lo co-resident ----------------
// Per K-chunk (k32): load Ahi,Alo (128x32) + Whi,Wlo (256x32) once; issue products
// HH, LH, HL into the same fp32 accumulators. 3-stage cp.async pipeline.
#define K3_ROWB   80
#define K3_AHI    0
#define K3_ALO    10240
#define K3_WHI    20480
#define K3_WLO    40960
#define K3_STG    61440
#define K3_DSMEM  (3*K3_STG)   // 184320

template<int MODE>
__launch_bounds__(256, 1)
__global__ void k3_mma(const float* __restrict__ bias) {
    constexpr int N  = (MODE==0) ? 1088 : (MODE==1) ? 512 : 384;
    constexpr int K  = (MODE==0) ? 1920 : (MODE==1) ? 1536 : 1152;
    constexpr int M  = (MODE==0) ? E_EDGES : 2*E_EDGES;
    constexpr int KC = K / 32;
    const __nv_bfloat16* __restrict__ Whi = (MODE==0) ? g_wm0_hi : (MODE==1) ? g_wm1_hi : g_wm2_hi;
    const __nv_bfloat16* __restrict__ Wlo = (MODE==0) ? g_wm0_lo : (MODE==1) ? g_wm1_lo : g_wm2_lo;
    float* __restrict__ C = (MODE==0) ? g_x0 : (MODE==1) ? g_ym1 : g_ym2;

    extern __shared__ char dsm[];
    const uint32_t smb = smem_u32(dsm);
    const int tid = threadIdx.x;
    const int wid = tid >> 5, lane = tid & 31;
    const int n0 = blockIdx.x * 256;
    const int m0 = blockIdx.y * 128;
    const int wm = (wid & 1) * 64;     // 2 warps along M
    const int wn = (wid >> 1) * 64;    // 4 warps along N

    float acc[4][8][4];
    #pragma unroll
    for (int i = 0; i < 4; i++)
        #pragma unroll
        for (int j = 0; j < 8; j++)
            #pragma unroll
            for (int q = 0; q < 4; q++) acc[i][j][q] = 0.f;

    // precompute 12 load slots (768 rows x 4x16B each, 256 threads)
    const __nv_bfloat16* srcb[12];
    uint32_t dsto[12];
    #pragma unroll
    for (int i = 0; i < 12; i++) {
        int u = tid + 256*i;
        int row = u >> 2, slot = u & 3;
        if (row < 256) {
            int r = row & 127;
            bool hi = row < 128;
            int gr = m0 + r; if (gr >= M) gr = 0;
            long ab;
            if (MODE == 0)      ab = (long)gr*MP_STRIDE;
            else if (MODE == 1) ab = (long)(gr>>1)*MP_STRIDE + 1920 + (long)(gr&1)*1536;
            else                ab = (long)(gr>>1)*MP_STRIDE + 4992 + (long)(gr&1)*1152;
            srcb[i] = (hi ? g_mp_hi : g_mp_lo) + ab + slot*8;
            dsto[i] = (hi ? K3_AHI : K3_ALO) + r*K3_ROWB + slot*16;
        } else {
            bool hi = row < 512;
            int rr = row - (hi ? 256 : 512);
            int gn = n0 + rr; if (gn >= N) gn = N-1;
            srcb[i] = (hi ? Whi : Wlo) + (long)gn*K + slot*8;
            dsto[i] = (hi ? K3_WHI : K3_WLO) + rr*K3_ROWB + slot*16;
        }
    }

    auto issue = [&](int c) {
        if (c < KC) {
            int k0 = c * 32;
            uint32_t st = smb + (c % 3) * K3_STG;
            #pragma unroll
            for (int i = 0; i < 12; i++)
                cp16(st + dsto[i], srcb[i] + k0);
        }
        asm volatile("cp.async.commit_group;" ::: "memory");
    };

    issue(0); issue(1);

    const int a_row = lane & 15, a_kh = lane >> 4;
    const int b_nl  = (lane & 7) | ((lane >> 4) << 3);
    const int b_kh  = (lane >> 3) & 1;

    for (int c = 0; c < KC; c++) {
        uint32_t st = smb + (c % 3) * K3_STG;
        asm volatile("cp.async.wait_group 1;" ::: "memory");
        __syncthreads();
        issue(c + 2);

        uint32_t aH = st + K3_AHI + (wm + a_row)*K3_ROWB + a_kh*16;
        uint32_t aL = st + K3_ALO + (wm + a_row)*K3_ROWB + a_kh*16;
        uint32_t bH = st + K3_WHI + (wn + b_nl)*K3_ROWB + b_kh*16;
        uint32_t bL = st + K3_WLO + (wn + b_nl)*K3_ROWB + b_kh*16;
        #pragma unroll
        for (int ks = 0; ks < 2; ks++) {
            uint32_t afH[4][4], bfH[4][4], tmp[4][4];
            #pragma unroll
            for (int mi = 0; mi < 4; mi++) ldm_x4(aH + ks*32 + mi*16*K3_ROWB, afH[mi]);
            #pragma unroll
            for (int nf = 0; nf < 4; nf++) ldm_x4(bH + ks*32 + nf*16*K3_ROWB, bfH[nf]);
            #pragma unroll
            for (int mi = 0; mi < 4; mi++)
                #pragma unroll
                for (int ni = 0; ni < 8; ni++)
                    mma16816(acc[mi][ni], afH[mi], bfH[ni>>1][(ni&1)*2], bfH[ni>>1][(ni&1)*2+1]);
            // A-lo x W-hi
            #pragma unroll
            for (int mi = 0; mi < 4; mi++) ldm_x4(aL + ks*32 + mi*16*K3_ROWB, tmp[mi]);
            #pragma unroll
            for (int mi = 0; mi < 4; mi++)
                #pragma unroll
                for (int ni = 0; ni < 8; ni++)
                    mma16816(acc[mi][ni], tmp[mi], bfH[ni>>1][(ni&1)*2], bfH[ni>>1][(ni&1)*2+1]);
            // A-hi x W-lo
            #pragma unroll
            for (int nf = 0; nf < 4; nf++) ldm_x4(bL + ks*32 + nf*16*K3_ROWB, tmp[nf]);
            #pragma unroll
            for (int mi = 0; mi < 4; mi++)
                #pragma unroll
                for (int ni = 0; ni < 8; ni++)
                    mma16816(acc[mi][ni], afH[mi], tmp[ni>>1][(ni&1)*2], tmp[ni>>1][(ni&1)*2+1]);
        }
    }

    // epilogue
    int tg = lane >> 2, tig = lane & 3;
    #pragma unroll
    for (int mi = 0; mi < 4; mi++) {
        #pragma unroll
        for (int ni = 0; ni < 8; ni++) {
            int row = m0 + wm + 16*mi + tg;
            int col = n0 + wn + 8*ni + 2*tig;
            if (col < N) {
                float bx = 0.f, by = 0.f;
                if (MODE == 0) { float2 bb = *(const float2*)(bias + col); bx = bb.x; by = bb.y; }
                if (row < M) {
                    float2 v = make_float2(acc[mi][ni][0] + bx, acc[mi][ni][1] + by);
                    *(float2*)(C + (long)row*N + col) = v;
                }
                if (row + 8 < M) {
                    float2 v = make_float2(acc[mi][ni][2] + bx, acc[mi][ni][3] + by);
                    *(float2*)(C + (long)(row+8)*N + col) = v;
                }
            }
        }
    }
}

// ---------------- K5: recombine+gate (fused) + Wigner back + projection ----------------
__launch_bounds__(256)
__global__ void k5_out(const float* __restrict__ wig,
                       const float* __restrict__ pw, const float* __restrict__ pb,
                       float* __restrict__ out) {
    __shared__ float s_full[2*25*64];
    __shared__ float s_buf[128*65];
    int e0 = blockIdx.x * 2;
    int tid = threadIdx.x;
    float* s_w  = s_buf;
    float* s_hl = s_buf + 950;

    for (int idx = tid; idx < 950; idx += 256) {
        int e = idx / 475, rem = idx - e*475;
        int r = rem / 25, n = rem - r*25;
        s_w[idx] = wig[(long)(e0+e)*625 + c_MASK[r]*25 + n];
    }
    // fused K4: build hl directly from GEMM outputs
    for (int idx = tid; idx < 2432; idx += 256) {
        int e = idx / 1216, rem = idx - e*1216;
        int j = rem >> 6, i = rem & 63;
        const float* x0 = g_x0  + (long)(e0+e)*X0_DIM;
        const float* y1 = g_ym1 + (long)(e0+e)*1024;
        const float* y2 = g_ym2 + (long)(e0+e)*768;
        float val;
        if (j < 5)        val = x0[768 + (j<<6) + i];
        else if (j < 9)  { int jj = j-5;  val = y1[jj*64 + i]       - y1[768 + jj*64 + i]; }
        else if (j < 13) { int jj = j-9;  val = y1[512 + jj*64 + i] + y1[256 + jj*64 + i]; }
        else if (j < 16) { int jj = j-13; val = y2[jj*64 + i]       - y2[576 + jj*64 + i]; }
        else             { int jj = j-16; val = y2[384 + jj*64 + i] + y2[192 + jj*64 + i]; }
        if (j == 0) {
            val = val * sigm(val);
        } else {
            float gsrc = x0[512 + (c_LPERM[j]-1)*64 + i];
            val *= sigm(gsrc);
        }
        s_hl[e*1216 + c_PERM[j]*64 + i] = val;
    }
    __syncthreads();
    for (int idx = tid; idx < 3200; idx += 256) {
        int e = idx / 1600, rem = idx - e*1600;
        int n = rem >> 6, i = rem & 63;
        float acc = 0.f;
        #pragma unroll
        for (int r = 0; r < 19; r++)
            acc += s_w[e*475 + r*25 + n] * s_hl[e*1216 + r*64 + i];
        s_full[idx] = acc;
    }
    __syncthreads();

    int o = tid & 127, ph = tid >> 7;
    for (int l = 0; l < 5; l++) {
        __syncthreads();
        for (int idx = tid; idx < 8192; idx += 256) {
            int oo = idx >> 6, ii = idx & 63;
            s_buf[oo*65 + ii] = pw[l*8192 + idx];
        }
        __syncthreads();
        int nrows = 2*l + 1, nstart = l*l;
        int npairs = 2*nrows;
        const float* pwrow = &s_buf[o*65];
        for (int p = ph; p < npairs; p += 2) {
            int e = p & 1, nr = p >> 1;
            const float* fu = &s_full[(e*25 + nstart + nr)*64];
            float acc = 0.f;
            #pragma unroll
            for (int i0 = 0; i0 < 64; i0 += 4) {
                float4 f = *(const float4*)(fu + i0);
                acc += f.x*pwrow[i0] + f.y*pwrow[i0+1] + f.z*pwrow[i0+2] + f.w*pwrow[i0+3];
            }
            if (l == 0) acc += pb[o];
            out[(long)(e0+e)*3200 + (nstart+nr)*128 + o] = acc;
        }
    }
}

// ---------------- launch ----------------
extern "C" void kernel_launch(void* const* d_in, const int* in_sizes, int n_in,
                              void* d_out, int out_size) {
    const float* x    = (const float*)d_in[0];
    const float* ef   = (const float*)d_in[1];
    const float* ed   = (const float*)d_in[2];
    const float* wig  = (const float*)d_in[3];
    const float* semb = (const float*)d_in[4];
    const float* temb = (const float*)d_in[5];
    const float* w1   = (const float*)d_in[6];
    const float* b1   = (const float*)d_in[7];
    const float* g1   = (const float*)d_in[8];
    const float* bb1  = (const float*)d_in[9];
    const float* w2   = (const float*)d_in[10];
    const float* b2   = (const float*)d_in[11];
    const float* g2   = (const float*)d_in[12];
    const float* bb2  = (const float*)d_in[13];
    const float* w3   = (const float*)d_in[14];
    const float* b3   = (const float*)d_in[15];
    const float* wm0  = (const float*)d_in[16];
    const float* bm0  = (const float*)d_in[17];
    const float* wm1  = (const float*)d_in[18];
    const float* wm2  = (const float*)d_in[19];
    const float* pw   = (const float*)d_in[20];
    const float* pb   = (const float*)d_in[21];
    const int*   an   = (const int*)d_in[22];
    const int*   ei   = (const int*)d_in[23];
    float* out = (float*)d_out;

    static bool attr_done = false;
    if (!attr_done) {
        cudaFuncSetAttribute(k3_mma<0>, cudaFuncAttributeMaxDynamicSharedMemorySize, K3_DSMEM);
        cudaFuncSetAttribute(k3_mma<1>, cudaFuncAttributeMaxDynamicSharedMemorySize, K3_DSMEM);
        cudaFuncSetAttribute(k3_mma<2>, cudaFuncAttributeMaxDynamicSharedMemorySize, K3_DSMEM);
        attr_done = true;
    }

    // K0: small transposes + weight bf16 splits
    ktrans<<<(128*384  + 255)/256, 256>>>(w1, 128,  384, 0);
    ktrans<<<(128*128  + 255)/256, 256>>>(w2, 128,  128, 1);
    ktrans<<<(1920*128 + 255)/256, 256>>>(w3, 1920, 128, 2);
    kconv<<<(1088*1920 + 255)/256, 256>>>(wm0, 1088*1920, 0);
    kconv<<<(512*1536  + 255)/256, 256>>>(wm1, 512*1536,  1);
    kconv<<<(384*1152  + 255)/256, 256>>>(wm2, 384*1152,  2);

    // K1: radial MLP
    k1_radial<<<E_EDGES/16, 256>>>(ed, semb, temb, b1, g1, bb1, b2, g2, bb2, b3, an, ei);

    // K2: msg * w_rad + Wigner forward (permuted, bf16-split store)
    k2_wfwd<<<E_EDGES, 256>>>(x, ef, wig, ei);

    // K3: tensor-core (mma.sync) GEMMs
    k3_mma<0><<<dim3(5, 79),  256, K3_DSMEM>>>(bm0);
    k3_mma<1><<<dim3(2, 157), 256, K3_DSMEM>>>(nullptr);
    k3_mma<2><<<dim3(2, 157), 256, K3_DSMEM>>>(nullptr);

    // K5: fused recombine + Wigner back + projection
    k5_out<<<E_EDGES/2, 256>>>(wig, pw, pb, out);
}

// round 6
// speedup vs baseline: 1.7086x; 1.1199x over previous
#include <cuda_runtime.h>
#include <cuda_bf16.h>
#include <cstdint>

// ---------------- problem constants ----------------
#define E_EDGES   10000
#define NRED      19
#define MP_STRIDE (NRED*384)   // 7296
#define X0_DIM    1088

// ---------------- scratch (__device__ globals) ----------------
__device__ float g_w1T [384*128];
__device__ float g_w2T [128*128];
__device__ float g_w3T [128*1920];
__device__ __nv_bfloat16 g_wm0_hi[1088*1920];
__device__ __nv_bfloat16 g_wm0_lo[1088*1920];
__device__ __nv_bfloat16 g_wm1_hi[512*1536];
__device__ __nv_bfloat16 g_wm1_lo[512*1536];
__device__ __nv_bfloat16 g_wm2_hi[384*1152];
__device__ __nv_bfloat16 g_wm2_lo[384*1152];
__device__ float g_wrad[(long)E_EDGES*1920];
__device__ __nv_bfloat16 g_mp_hi[(long)E_EDGES*MP_STRIDE];
__device__ __nv_bfloat16 g_mp_lo[(long)E_EDGES*MP_STRIDE];
__device__ float g_x0  [(long)E_EDGES*X0_DIM];
__device__ float g_ym1 [(long)E_EDGES*2*512];
__device__ float g_ym2 [(long)E_EDGES*2*384];

// permutation tables
__constant__ int c_MASKP[19] = {0,2,6,12,20, 3,7,13,21, 1,5,11,19, 8,14,22, 4,10,18};
__constant__ int c_MASK [19] = {0,1,2,3,4,5,6,7,8,10,11,12,13,14,18,19,20,21,22};
__constant__ int c_PERM [19] = {0,2,6,11,16, 3,7,12,17, 1,5,10,15, 8,13,18, 4,9,14};
__constant__ int c_LPERM[19] = {0,1,2,3,4, 1,2,3,4, 1,2,3,4, 2,3,4, 2,3,4};
__constant__ int c_LFULL[25] = {0,1,1,1,2,2,2,2,2,3,3,3,3,3,3,3,4,4,4,4,4,4,4,4,4};

__device__ __forceinline__ float sigm(float x){ return 1.f/(1.f+__expf(-x)); }

__device__ __forceinline__ uint32_t smem_u32(const void* p) {
    uint32_t a;
    asm("{ .reg .u64 t; cvta.to.shared.u64 t, %1; cvt.u32.u64 %0, t; }" : "=r"(a) : "l"(p));
    return a;
}
__device__ __forceinline__ void cp16(uint32_t dst, const void* src) {
    asm volatile("cp.async.cg.shared.global [%0], [%1], 16;" :: "r"(dst), "l"(src));
}
__device__ __forceinline__ void ldm_x4(uint32_t addr, uint32_t* r) {
    asm volatile("ldmatrix.sync.aligned.m8n8.x4.shared.b16 {%0,%1,%2,%3}, [%4];"
                 : "=r"(r[0]), "=r"(r[1]), "=r"(r[2]), "=r"(r[3]) : "r"(addr));
}
__device__ __forceinline__ void mma16816(float* d, const uint32_t* a, uint32_t b0, uint32_t b1) {
    asm volatile("mma.sync.aligned.m16n8k16.row.col.f32.bf16.bf16.f32 "
                 "{%0,%1,%2,%3}, {%4,%5,%6,%7}, {%8,%9}, {%0,%1,%2,%3};"
                 : "+f"(d[0]), "+f"(d[1]), "+f"(d[2]), "+f"(d[3])
                 : "r"(a[0]), "r"(a[1]), "r"(a[2]), "r"(a[3]), "r"(b0), "r"(b1));
}

// ---------------- K0 (fused): transposes + bf16 splits, single launch ----------------
__global__ void k0_fused(const float* __restrict__ w1, const float* __restrict__ w2,
                         const float* __restrict__ w3, const float* __restrict__ wm0,
                         const float* __restrict__ wm1, const float* __restrict__ wm2) {
    long i = (long)blockIdx.x*256 + threadIdx.x;
    if (i < 49152) { int r = (int)(i/384), c = (int)(i%384); g_w1T[c*128+r] = w1[i]; return; }
    i -= 49152;
    if (i < 16384) { int r = (int)(i/128), c = (int)(i%128); g_w2T[c*128+r] = w2[i]; return; }
    i -= 16384;
    if (i < 245760) { int r = (int)(i/128), c = (int)(i%128); g_w3T[c*1920+r] = w3[i]; return; }
    i -= 245760;
    if (i < 2088960) {
        float v = wm0[i]; __nv_bfloat16 h = __float2bfloat16(v);
        g_wm0_hi[i] = h; g_wm0_lo[i] = __float2bfloat16(v - __bfloat162float(h));
        return;
    }
    i -= 2088960;
    if (i < 786432) {
        float v = wm1[i]; __nv_bfloat16 h = __float2bfloat16(v);
        g_wm1_hi[i] = h; g_wm1_lo[i] = __float2bfloat16(v - __bfloat162float(h));
        return;
    }
    i -= 786432;
    if (i < 442368) {
        float v = wm2[i]; __nv_bfloat16 h = __float2bfloat16(v);
        g_wm2_hi[i] = h; g_wm2_lo[i] = __float2bfloat16(v - __bfloat162float(h));
    }
}

// ---------------- K1: radial MLP (16 edges/block) ----------------
__device__ __forceinline__ void ln_silu16(float* buf, const float* __restrict__ g, const float* __restrict__ b) {
    int tid = threadIdx.x, w = tid >> 5, lane = tid & 31;
    for (int le = w; le < 16; le += 8) {
        float s = 0.f, s2 = 0.f;
        #pragma unroll
        for (int q = 0; q < 4; q++) { float v = buf[le*128 + lane + 32*q]; s += v; s2 += v*v; }
        #pragma unroll
        for (int off = 16; off > 0; off >>= 1) {
            s  += __shfl_xor_sync(0xffffffffu, s,  off);
            s2 += __shfl_xor_sync(0xffffffffu, s2, off);
        }
        float mu = s * (1.f/128.f);
        float var = s2 * (1.f/128.f) - mu*mu;
        float rstd = rsqrtf(var + 1e-5f);
        #pragma unroll
        for (int q = 0; q < 4; q++) {
            int oo = lane + 32*q;
            float v = buf[le*128 + oo];
            v = (v - mu)*rstd*g[oo] + b[oo];
            buf[le*128 + oo] = v * sigm(v);
        }
    }
}

__launch_bounds__(256)
__global__ void k1_radial(const float* __restrict__ ed,
                          const float* __restrict__ semb, const float* __restrict__ temb,
                          const float* __restrict__ b1, const float* __restrict__ g1, const float* __restrict__ bb1,
                          const float* __restrict__ b2, const float* __restrict__ g2, const float* __restrict__ bb2,
                          const float* __restrict__ b3,
                          const int* __restrict__ an, const int* __restrict__ ei) {
    __shared__ float xe[16*384];
    __shared__ float h1[16*128];
    __shared__ float h2[16*128];
    int e0 = blockIdx.x * 16;
    int tid = threadIdx.x;

    for (int idx = tid; idx < 16*384; idx += 256) {
        int le = idx / 384, c = idx - le*384;
        int e = e0 + le;
        float v;
        if (c < 128)       v = ed[e*128 + c];
        else if (c < 256)  v = semb[an[ei[e]]*128 + (c-128)];
        else               v = temb[an[ei[E_EDGES + e]]*128 + (c-256)];
        xe[idx] = v;
    }
    __syncthreads();

    int o = tid & 127, hh = tid >> 7;
    {
        float acc[8]; float bv = b1[o];
        #pragma unroll
        for (int j = 0; j < 8; j++) acc[j] = bv;
        #pragma unroll 4
        for (int k = 0; k < 384; k++) {
            float wv = g_w1T[k*128 + o];
            #pragma unroll
            for (int j = 0; j < 8; j++) acc[j] += wv * xe[(hh*8+j)*384 + k];
        }
        #pragma unroll
        for (int j = 0; j < 8; j++) h1[(hh*8+j)*128 + o] = acc[j];
    }
    __syncthreads();
    ln_silu16(h1, g1, bb1);
    __syncthreads();
    {
        float acc[8]; float bv = b2[o];
        #pragma unroll
        for (int j = 0; j < 8; j++) acc[j] = bv;
        #pragma unroll 4
        for (int k = 0; k < 128; k++) {
            float wv = g_w2T[k*128 + o];
            #pragma unroll
            for (int j = 0; j < 8; j++) acc[j] += wv * h1[(hh*8+j)*128 + k];
        }
        #pragma unroll
        for (int j = 0; j < 8; j++) h2[(hh*8+j)*128 + o] = acc[j];
    }
    __syncthreads();
    ln_silu16(h2, g2, bb2);
    __syncthreads();
    for (int oo = tid; oo < 1920; oo += 256) {
        float acc[16];
        #pragma unroll
        for (int le = 0; le < 16; le++) acc[le] = 0.f;
        #pragma unroll 4
        for (int k = 0; k < 128; k++) {
            float wv = g_w3T[k*1920 + oo];
            #pragma unroll
            for (int le = 0; le < 16; le++) acc[le] += wv * h2[le*128 + k];
        }
        float bv = b3[oo];
        #pragma unroll
        for (int le = 0; le < 16; le++)
            g_wrad[(long)(e0+le)*1920 + oo] = acc[le] + bv;
    }
}

// ---------------- K2: msg build * w_rad, Wigner fwd, permuted bf16-split store ----------------
__launch_bounds__(256)
__global__ void k2_wfwd(const float* __restrict__ x, const float* __restrict__ ef,
                        const float* __restrict__ wig, const int* __restrict__ ei) {
    __shared__ float msg[25*384];
    __shared__ float wp[19*25];
    int e = blockIdx.x, tid = threadIdx.x;
    int src = ei[e], tgt = ei[E_EDGES + e];

    for (int idx = tid; idx < 475; idx += 256) {
        int j = idx / 25, n = idx - j*25;
        wp[idx] = wig[(long)e*625 + c_MASKP[j]*25 + n];
    }
    const float4* x4  = (const float4*)x;
    const float4* ef4 = (const float4*)ef;
    const float4* wr4 = (const float4*)(g_wrad + (long)e*1920);
    float4* msg4 = (float4*)msg;
    for (int idx = tid; idx < 25*96; idx += 256) {
        int n = idx / 96, c4 = idx - n*96;
        float4 v;
        if (c4 < 32)      v = x4[(long)src*800 + n*32 + c4];
        else if (c4 < 64) v = x4[(long)tgt*800 + n*32 + (c4-32)];
        else              v = ef4[(long)e*800 + n*32 + (c4-64)];
        float4 w = wr4[c_LFULL[n]*96 + c4];
        v.x *= w.x; v.y *= w.y; v.z *= w.z; v.w *= w.w;
        msg4[idx] = v;
    }
    __syncthreads();

    const float4* m4 = (const float4*)msg;
    for (int idx = tid; idx < 19*96; idx += 256) {
        float4 acc = make_float4(0.f,0.f,0.f,0.f);
        int j = idx / 96, c4 = idx - j*96;
        #pragma unroll
        for (int n = 0; n < 25; n++) {
            float w = wp[j*25 + n];
            float4 m = m4[n*96 + c4];
            acc.x += w*m.x; acc.y += w*m.y; acc.z += w*m.z; acc.w += w*m.w;
        }
        long base = (long)e*MP_STRIDE + (long)idx*4;
        __nv_bfloat16 h0 = __float2bfloat16(acc.x);
        __nv_bfloat16 h1 = __float2bfloat16(acc.y);
        __nv_bfloat16 h2 = __float2bfloat16(acc.z);
        __nv_bfloat16 h3 = __float2bfloat16(acc.w);
        __nv_bfloat162 hp0; hp0.x = h0; hp0.y = h1;
        __nv_bfloat162 hp1; hp1.x = h2; hp1.y = h3;
        ((__nv_bfloat162*)(g_mp_hi + base))[0] = hp0;
        ((__nv_bfloat162*)(g_mp_hi + base))[1] = hp1;
        __nv_bfloat162 lp0, lp1;
        lp0.x = __float2bfloat16(acc.x - __bfloat162float(h0));
        lp0.y = __float2bfloat16(acc.y - __bfloat162float(h1));
        lp1.x = __float2bfloat16(acc.z - __bfloat162float(h2));
        lp1.y = __float2bfloat16(acc.w - __bfloat162float(h3));
        ((__nv_bfloat162*)(g_mp_lo + base))[0] = lp0;
        ((__nv_bfloat162*)(g_mp_lo + base))[1] = lp1;
    }
}

// ---------------- K3: mma.sync bf16x3 GEMM, CTA 128x128, 2 CTAs/SM ----------------
// Per K-chunk (32): stage holds Ahi,Alo (128x32) + Whi,Wlo (128x32) = 40KB.
// Products HH, HL, LH accumulate in fp32 regs; A-lo frags overwrite A-hi frags.
#define K3_ROWB   80
#define K3_STG    40960
#define K3_DSMEM  (2*K3_STG)   // 81920

template<int MODE>
__launch_bounds__(256, 2)
__global__ void k3_mma(const float* __restrict__ bias) {
    constexpr int N  = (MODE==0) ? 1088 : (MODE==1) ? 512 : 384;
    constexpr int K  = (MODE==0) ? 1920 : (MODE==1) ? 1536 : 1152;
    constexpr int M  = (MODE==0) ? E_EDGES : 2*E_EDGES;
    constexpr int KC = K / 32;
    const __nv_bfloat16* __restrict__ Whi = (MODE==0) ? g_wm0_hi : (MODE==1) ? g_wm1_hi : g_wm2_hi;
    const __nv_bfloat16* __restrict__ Wlo = (MODE==0) ? g_wm0_lo : (MODE==1) ? g_wm1_lo : g_wm2_lo;
    float* __restrict__ C = (MODE==0) ? g_x0 : (MODE==1) ? g_ym1 : g_ym2;

    extern __shared__ char dsm[];
    const uint32_t smb = smem_u32(dsm);
    const int tid = threadIdx.x;
    const int wid = tid >> 5, lane = tid & 31;
    const int n0 = blockIdx.x * 128;
    const int m0 = blockIdx.y * 128;
    const int wm = (wid & 1) * 64;     // 2 warps along M
    const int wn = (wid >> 1) * 32;    // 4 warps along N

    float acc[4][4][4];
    #pragma unroll
    for (int i = 0; i < 4; i++)
        #pragma unroll
        for (int j = 0; j < 4; j++)
            #pragma unroll
            for (int q = 0; q < 4; q++) acc[i][j][q] = 0.f;

    // load-slot pointers: 256 threads cover 128 A-rows + 128 W-rows x 4 slots, 2 j-halves
    const int lr = tid >> 2, slot = tid & 3;   // lr: 0..63
    const __nv_bfloat16* aP[2];
    const __nv_bfloat16* wP[2];
    #pragma unroll
    for (int j = 0; j < 2; j++) {
        int r = lr + 64*j;
        int gr = m0 + r; if (gr >= M) gr = 0;
        long ab;
        if (MODE == 0)      ab = (long)gr*MP_STRIDE;
        else if (MODE == 1) ab = (long)(gr>>1)*MP_STRIDE + 1920 + (long)(gr&1)*1536;
        else                ab = (long)(gr>>1)*MP_STRIDE + 4992 + (long)(gr&1)*1152;
        aP[j] = g_mp_hi + ab + slot*8;
        int gn = n0 + r; if (gn >= N) gn = N-1;
        wP[j] = Whi + (long)gn*K + slot*8;
    }
    const long adel = (const __nv_bfloat16*)g_mp_lo - (const __nv_bfloat16*)g_mp_hi;
    const long wdel = Wlo - Whi;

    auto issue = [&](int c) {
        if (c < KC) {
            int k0 = c * 32;
            uint32_t st = smb + (c & 1) * K3_STG;
            #pragma unroll
            for (int j = 0; j < 2; j++) {
                uint32_t d = st + (lr + 64*j)*K3_ROWB + slot*16;
                cp16(d,         aP[j] + k0);           // A-hi
                cp16(d + 10240, aP[j] + adel + k0);    // A-lo
                cp16(d + 20480, wP[j] + k0);           // W-hi
                cp16(d + 30720, wP[j] + wdel + k0);    // W-lo
            }
        }
        asm volatile("cp.async.commit_group;" ::: "memory");
    };

    issue(0); issue(1);

    const int a_row = lane & 15, a_kh = lane >> 4;
    const int b_nl  = (lane & 7) | ((lane >> 4) << 3);
    const int b_kh  = (lane >> 3) & 1;

    for (int c = 0; c < KC; c++) {
        uint32_t st = smb + (c & 1) * K3_STG;
        asm volatile("cp.async.wait_group 1;" ::: "memory");
        __syncthreads();
        uint32_t aH = st +         (wm + a_row)*K3_ROWB + a_kh*16;
        uint32_t bH = st + 20480 + (wn + b_nl)*K3_ROWB + b_kh*16;
        #pragma unroll
        for (int ks = 0; ks < 2; ks++) {
            uint32_t af[4][4], bf[2][4], tb[2][4];
            #pragma unroll
            for (int mi = 0; mi < 4; mi++) ldm_x4(aH + ks*32 + mi*16*K3_ROWB, af[mi]);
            #pragma unroll
            for (int nf = 0; nf < 2; nf++) ldm_x4(bH + ks*32 + nf*16*K3_ROWB, bf[nf]);
            // A-hi x W-hi
            #pragma unroll
            for (int mi = 0; mi < 4; mi++)
                #pragma unroll
                for (int ni = 0; ni < 4; ni++)
                    mma16816(acc[mi][ni], af[mi], bf[ni>>1][(ni&1)*2], bf[ni>>1][(ni&1)*2+1]);
            // A-hi x W-lo
            #pragma unroll
            for (int nf = 0; nf < 2; nf++) ldm_x4(bH + 10240 + ks*32 + nf*16*K3_ROWB, tb[nf]);
            #pragma unroll
            for (int mi = 0; mi < 4; mi++)
                #pragma unroll
                for (int ni = 0; ni < 4; ni++)
                    mma16816(acc[mi][ni], af[mi], tb[ni>>1][(ni&1)*2], tb[ni>>1][(ni&1)*2+1]);
            // A-lo x W-hi (overwrite af)
            #pragma unroll
            for (int mi = 0; mi < 4; mi++) ldm_x4(aH + 10240 + ks*32 + mi*16*K3_ROWB, af[mi]);
            #pragma unroll
            for (int mi = 0; mi < 4; mi++)
                #pragma unroll
                for (int ni = 0; ni < 4; ni++)
                    mma16816(acc[mi][ni], af[mi], bf[ni>>1][(ni&1)*2], bf[ni>>1][(ni&1)*2+1]);
        }
        __syncthreads();
        issue(c + 2);
    }

    // epilogue
    int tg = lane >> 2, tig = lane & 3;
    #pragma unroll
    for (int mi = 0; mi < 4; mi++) {
        #pragma unroll
        for (int ni = 0; ni < 4; ni++) {
            int row = m0 + wm + 16*mi + tg;
            int col = n0 + wn + 8*ni + 2*tig;
            if (col < N) {
                float bx = 0.f, by = 0.f;
                if (MODE == 0) { float2 bb = *(const float2*)(bias + col); bx = bb.x; by = bb.y; }
                if (row < M) {
                    float2 v = make_float2(acc[mi][ni][0] + bx, acc[mi][ni][1] + by);
                    *(float2*)(C + (long)row*N + col) = v;
                }
                if (row + 8 < M) {
                    float2 v = make_float2(acc[mi][ni][2] + bx, acc[mi][ni][3] + by);
                    *(float2*)(C + (long)(row+8)*N + col) = v;
                }
            }
        }
    }
}

// ---------------- K5: recombine+gate (fused) + Wigner back + projection ----------------
__launch_bounds__(256)
__global__ void k5_out(const float* __restrict__ wig,
                       const float* __restrict__ pw, const float* __restrict__ pb,
                       float* __restrict__ out) {
    __shared__ float s_full[2*25*64];
    __shared__ float s_buf[128*65];
    int e0 = blockIdx.x * 2;
    int tid = threadIdx.x;
    float* s_w  = s_buf;
    float* s_hl = s_buf + 950;

    for (int idx = tid; idx < 950; idx += 256) {
        int e = idx / 475, rem = idx - e*475;
        int r = rem / 25, n = rem - r*25;
        s_w[idx] = wig[(long)(e0+e)*625 + c_MASK[r]*25 + n];
    }
    for (int idx = tid; idx < 2432; idx += 256) {
        int e = idx / 1216, rem = idx - e*1216;
        int j = rem >> 6, i = rem & 63;
        const float* x0 = g_x0  + (long)(e0+e)*X0_DIM;
        const float* y1 = g_ym1 + (long)(e0+e)*1024;
        const float* y2 = g_ym2 + (long)(e0+e)*768;
        float val;
        if (j < 5)        val = x0[768 + (j<<6) + i];
        else if (j < 9)  { int jj = j-5;  val = y1[jj*64 + i]       - y1[768 + jj*64 + i]; }
        else if (j < 13) { int jj = j-9;  val = y1[512 + jj*64 + i] + y1[256 + jj*64 + i]; }
        else if (j < 16) { int jj = j-13; val = y2[jj*64 + i]       - y2[576 + jj*64 + i]; }
        else             { int jj = j-16; val = y2[384 + jj*64 + i] + y2[192 + jj*64 + i]; }
        if (j == 0) {
            val = val * sigm(val);
        } else {
            float gsrc = x0[512 + (c_LPERM[j]-1)*64 + i];
            val *= sigm(gsrc);
        }
        s_hl[e*1216 + c_PERM[j]*64 + i] = val;
    }
    __syncthreads();
    for (int idx = tid; idx < 3200; idx += 256) {
        int e = idx / 1600, rem = idx - e*1600;
        int n = rem >> 6, i = rem & 63;
        float acc = 0.f;
        #pragma unroll
        for (int r = 0; r < 19; r++)
            acc += s_w[e*475 + r*25 + n] * s_hl[e*1216 + r*64 + i];
        s_full[idx] = acc;
    }
    __syncthreads();

    int o = tid & 127, ph = tid >> 7;
    for (int l = 0; l < 5; l++) {
        __syncthreads();
        for (int idx = tid; idx < 8192; idx += 256) {
            int oo = idx >> 6, ii = idx & 63;
            s_buf[oo*65 + ii] = pw[l*8192 + idx];
        }
        __syncthreads();
        int nrows = 2*l + 1, nstart = l*l;
        int npairs = 2*nrows;
        const float* pwrow = &s_buf[o*65];
        for (int p = ph; p < npairs; p += 2) {
            int e = p & 1, nr = p >> 1;
            const float* fu = &s_full[(e*25 + nstart + nr)*64];
            float acc = 0.f;
            #pragma unroll
            for (int i0 = 0; i0 < 64; i0 += 4) {
                float4 f = *(const float4*)(fu + i0);
                acc += f.x*pwrow[i0] + f.y*pwrow[i0+1] + f.z*pwrow[i0+2] + f.w*pwrow[i0+3];
            }
            if (l == 0) acc += pb[o];
            out[(long)(e0+e)*3200 + (nstart+nr)*128 + o] = acc;
        }
    }
}

// ---------------- launch ----------------
extern "C" void kernel_launch(void* const* d_in, const int* in_sizes, int n_in,
                              void* d_out, int out_size) {
    const float* x    = (const float*)d_in[0];
    const float* ef   = (const float*)d_in[1];
    const float* ed   = (const float*)d_in[2];
    const float* wig  = (const float*)d_in[3];
    const float* semb = (const float*)d_in[4];
    const float* temb = (const float*)d_in[5];
    const float* w1   = (const float*)d_in[6];
    const float* b1   = (const float*)d_in[7];
    const float* g1   = (const float*)d_in[8];
    const float* bb1  = (const float*)d_in[9];
    const float* w2   = (const float*)d_in[10];
    const float* b2   = (const float*)d_in[11];
    const float* g2   = (const float*)d_in[12];
    const float* bb2  = (const float*)d_in[13];
    const float* w3   = (const float*)d_in[14];
    const float* b3   = (const float*)d_in[15];
    const float* wm0  = (const float*)d_in[16];
    const float* bm0  = (const float*)d_in[17];
    const float* wm1  = (const float*)d_in[18];
    const float* wm2  = (const float*)d_in[19];
    const float* pw   = (const float*)d_in[20];
    const float* pb   = (const float*)d_in[21];
    const int*   an   = (const int*)d_in[22];
    const int*   ei   = (const int*)d_in[23];
    float* out = (float*)d_out;

    static bool attr_done = false;
    if (!attr_done) {
        cudaFuncSetAttribute(k3_mma<0>, cudaFuncAttributeMaxDynamicSharedMemorySize, K3_DSMEM);
        cudaFuncSetAttribute(k3_mma<1>, cudaFuncAttributeMaxDynamicSharedMemorySize, K3_DSMEM);
        cudaFuncSetAttribute(k3_mma<2>, cudaFuncAttributeMaxDynamicSharedMemorySize, K3_DSMEM);
        attr_done = true;
    }

    // launch 0: fused prelude (transposes + bf16 splits)
    k0_fused<<<14176, 256>>>(w1, w2, w3, wm0, wm1, wm2);

    // launch 1: radial MLP
    k1_radial<<<E_EDGES/16, 256>>>(ed, semb, temb, b1, g1, bb1, b2, g2, bb2, b3, an, ei);

    // launch 2: msg * w_rad + Wigner forward (permuted, bf16-split store)
    k2_wfwd<<<E_EDGES, 256>>>(x, ef, wig, ei);

    // launches 3-5: tensor-core GEMMs (k3<0> last so ncu -s 5 captures it)
    k3_mma<2><<<dim3(3, 157), 256, K3_DSMEM>>>(nullptr);
    k3_mma<1><<<dim3(4, 157), 256, K3_DSMEM>>>(nullptr);
    k3_mma<0><<<dim3(9, 79),  256, K3_DSMEM>>>(bm0);

    // launch 6: fused recombine + Wigner back + projection
    k5_out<<<E_EDGES/2, 256>>>(wig, pw, pb, out);
}

// round 7
// speedup vs baseline: 1.8303x; 1.0712x over previous
#include <cuda_runtime.h>
#include <cuda_bf16.h>
#include <cstdint>

// ---------------- problem constants ----------------
#define E_EDGES   10000
#define NRED      19
#define MP_STRIDE (NRED*384)   // 7296
#define X0_DIM    1088

// ---------------- scratch (__device__ globals) ----------------
__device__ float g_w1T [384*128];
__device__ float g_w2T [128*128];
__device__ float g_w3T [128*1920];
__device__ __nv_bfloat16 g_wm0_hi[1088*1920];
__device__ __nv_bfloat16 g_wm0_lo[1088*1920];
__device__ __nv_bfloat16 g_wm1_hi[512*1536];
__device__ __nv_bfloat16 g_wm1_lo[512*1536];
__device__ __nv_bfloat16 g_wm2_hi[384*1152];
__device__ __nv_bfloat16 g_wm2_lo[384*1152];
__device__ float g_wrad[(long)E_EDGES*1920];
__device__ __nv_bfloat16 g_mp_hi[(long)E_EDGES*MP_STRIDE];
__device__ __nv_bfloat16 g_mp_lo[(long)E_EDGES*MP_STRIDE];
__device__ float g_x0  [(long)E_EDGES*X0_DIM];
__device__ float g_ym1 [(long)E_EDGES*2*512];
__device__ float g_ym2 [(long)E_EDGES*2*384];

// permutation tables
__constant__ int c_MASKP[19] = {0,2,6,12,20, 3,7,13,21, 1,5,11,19, 8,14,22, 4,10,18};
__constant__ int c_MASK [19] = {0,1,2,3,4,5,6,7,8,10,11,12,13,14,18,19,20,21,22};
__constant__ int c_PERM [19] = {0,2,6,11,16, 3,7,12,17, 1,5,10,15, 8,13,18, 4,9,14};
__constant__ int c_LPERM[19] = {0,1,2,3,4, 1,2,3,4, 1,2,3,4, 2,3,4, 2,3,4};
__constant__ int c_LFULL[25] = {0,1,1,1,2,2,2,2,2,3,3,3,3,3,3,3,4,4,4,4,4,4,4,4,4};

__device__ __forceinline__ float sigm(float x){ return 1.f/(1.f+__expf(-x)); }

__device__ __forceinline__ uint32_t smem_u32(const void* p) {
    uint32_t a;
    asm("{ .reg .u64 t; cvta.to.shared.u64 t, %1; cvt.u32.u64 %0, t; }" : "=r"(a) : "l"(p));
    return a;
}
__device__ __forceinline__ void cp16(uint32_t dst, const void* src) {
    asm volatile("cp.async.cg.shared.global [%0], [%1], 16;" :: "r"(dst), "l"(src));
}
__device__ __forceinline__ void ldm_x4(uint32_t addr, uint32_t* r) {
    asm volatile("ldmatrix.sync.aligned.m8n8.x4.shared.b16 {%0,%1,%2,%3}, [%4];"
                 : "=r"(r[0]), "=r"(r[1]), "=r"(r[2]), "=r"(r[3]) : "r"(addr));
}
__device__ __forceinline__ void mma16816(float* d, const uint32_t* a, uint32_t b0, uint32_t b1) {
    asm volatile("mma.sync.aligned.m16n8k16.row.col.f32.bf16.bf16.f32 "
                 "{%0,%1,%2,%3}, {%4,%5,%6,%7}, {%8,%9}, {%0,%1,%2,%3};"
                 : "+f"(d[0]), "+f"(d[1]), "+f"(d[2]), "+f"(d[3])
                 : "r"(a[0]), "r"(a[1]), "r"(a[2]), "r"(a[3]), "r"(b0), "r"(b1));
}

// ---------------- K0 (fused): transposes + bf16 splits, single launch ----------------
__global__ void k0_fused(const float* __restrict__ w1, const float* __restrict__ w2,
                         const float* __restrict__ w3, const float* __restrict__ wm0,
                         const float* __restrict__ wm1, const float* __restrict__ wm2) {
    long i = (long)blockIdx.x*256 + threadIdx.x;
    if (i < 49152) { int r = (int)(i/384), c = (int)(i%384); g_w1T[c*128+r] = w1[i]; return; }
    i -= 49152;
    if (i < 16384) { int r = (int)(i/128), c = (int)(i%128); g_w2T[c*128+r] = w2[i]; return; }
    i -= 16384;
    if (i < 245760) { int r = (int)(i/128), c = (int)(i%128); g_w3T[c*1920+r] = w3[i]; return; }
    i -= 245760;
    if (i < 2088960) {
        float v = wm0[i]; __nv_bfloat16 h = __float2bfloat16(v);
        g_wm0_hi[i] = h; g_wm0_lo[i] = __float2bfloat16(v - __bfloat162float(h));
        return;
    }
    i -= 2088960;
    if (i < 786432) {
        float v = wm1[i]; __nv_bfloat16 h = __float2bfloat16(v);
        g_wm1_hi[i] = h; g_wm1_lo[i] = __float2bfloat16(v - __bfloat162float(h));
        return;
    }
    i -= 786432;
    if (i < 442368) {
        float v = wm2[i]; __nv_bfloat16 h = __float2bfloat16(v);
        g_wm2_hi[i] = h; g_wm2_lo[i] = __float2bfloat16(v - __bfloat162float(h));
    }
}

// ---------------- K1: radial MLP (16 edges/block) ----------------
__device__ __forceinline__ void ln_silu16(float* buf, const float* __restrict__ g, const float* __restrict__ b) {
    int tid = threadIdx.x, w = tid >> 5, lane = tid & 31;
    for (int le = w; le < 16; le += 8) {
        float s = 0.f, s2 = 0.f;
        #pragma unroll
        for (int q = 0; q < 4; q++) { float v = buf[le*128 + lane + 32*q]; s += v; s2 += v*v; }
        #pragma unroll
        for (int off = 16; off > 0; off >>= 1) {
            s  += __shfl_xor_sync(0xffffffffu, s,  off);
            s2 += __shfl_xor_sync(0xffffffffu, s2, off);
        }
        float mu = s * (1.f/128.f);
        float var = s2 * (1.f/128.f) - mu*mu;
        float rstd = rsqrtf(var + 1e-5f);
        #pragma unroll
        for (int q = 0; q < 4; q++) {
            int oo = lane + 32*q;
            float v = buf[le*128 + oo];
            v = (v - mu)*rstd*g[oo] + b[oo];
            buf[le*128 + oo] = v * sigm(v);
        }
    }
}

__launch_bounds__(256)
__global__ void k1_radial(const float* __restrict__ ed,
                          const float* __restrict__ semb, const float* __restrict__ temb,
                          const float* __restrict__ b1, const float* __restrict__ g1, const float* __restrict__ bb1,
                          const float* __restrict__ b2, const float* __restrict__ g2, const float* __restrict__ bb2,
                          const float* __restrict__ b3,
                          const int* __restrict__ an, const int* __restrict__ ei) {
    __shared__ float xe[16*384];
    __shared__ float h1[16*128];
    __shared__ float h2[16*128];
    int e0 = blockIdx.x * 16;
    int tid = threadIdx.x;

    for (int idx = tid; idx < 16*384; idx += 256) {
        int le = idx / 384, c = idx - le*384;
        int e = e0 + le;
        float v;
        if (c < 128)       v = ed[e*128 + c];
        else if (c < 256)  v = semb[an[ei[e]]*128 + (c-128)];
        else               v = temb[an[ei[E_EDGES + e]]*128 + (c-256)];
        xe[idx] = v;
    }
    __syncthreads();

    int o = tid & 127, hh = tid >> 7;
    {
        float acc[8]; float bv = b1[o];
        #pragma unroll
        for (int j = 0; j < 8; j++) acc[j] = bv;
        #pragma unroll 4
        for (int k = 0; k < 384; k++) {
            float wv = g_w1T[k*128 + o];
            #pragma unroll
            for (int j = 0; j < 8; j++) acc[j] += wv * xe[(hh*8+j)*384 + k];
        }
        #pragma unroll
        for (int j = 0; j < 8; j++) h1[(hh*8+j)*128 + o] = acc[j];
    }
    __syncthreads();
    ln_silu16(h1, g1, bb1);
    __syncthreads();
    {
        float acc[8]; float bv = b2[o];
        #pragma unroll
        for (int j = 0; j < 8; j++) acc[j] = bv;
        #pragma unroll 4
        for (int k = 0; k < 128; k++) {
            float wv = g_w2T[k*128 + o];
            #pragma unroll
            for (int j = 0; j < 8; j++) acc[j] += wv * h1[(hh*8+j)*128 + k];
        }
        #pragma unroll
        for (int j = 0; j < 8; j++) h2[(hh*8+j)*128 + o] = acc[j];
    }
    __syncthreads();
    ln_silu16(h2, g2, bb2);
    __syncthreads();
    for (int oo = tid; oo < 1920; oo += 256) {
        float acc[16];
        #pragma unroll
        for (int le = 0; le < 16; le++) acc[le] = 0.f;
        #pragma unroll 4
        for (int k = 0; k < 128; k++) {
            float wv = g_w3T[k*1920 + oo];
            #pragma unroll
            for (int le = 0; le < 16; le++) acc[le] += wv * h2[le*128 + k];
        }
        float bv = b3[oo];
        #pragma unroll
        for (int le = 0; le < 16; le++)
            g_wrad[(long)(e0+le)*1920 + oo] = acc[le] + bv;
    }
}

// ---------------- K2: msg build * w_rad, Wigner fwd, permuted bf16-split store ----------------
__launch_bounds__(256)
__global__ void k2_wfwd(const float* __restrict__ x, const float* __restrict__ ef,
                        const float* __restrict__ wig, const int* __restrict__ ei) {
    __shared__ float msg[25*384];
    __shared__ float wp[19*25];
    int e = blockIdx.x, tid = threadIdx.x;
    int src = ei[e], tgt = ei[E_EDGES + e];

    for (int idx = tid; idx < 475; idx += 256) {
        int j = idx / 25, n = idx - j*25;
        wp[idx] = wig[(long)e*625 + c_MASKP[j]*25 + n];
    }
    const float4* x4  = (const float4*)x;
    const float4* ef4 = (const float4*)ef;
    const float4* wr4 = (const float4*)(g_wrad + (long)e*1920);
    float4* msg4 = (float4*)msg;
    for (int idx = tid; idx < 25*96; idx += 256) {
        int n = idx / 96, c4 = idx - n*96;
        float4 v;
        if (c4 < 32)      v = x4[(long)src*800 + n*32 + c4];
        else if (c4 < 64) v = x4[(long)tgt*800 + n*32 + (c4-32)];
        else              v = ef4[(long)e*800 + n*32 + (c4-64)];
        float4 w = wr4[c_LFULL[n]*96 + c4];
        v.x *= w.x; v.y *= w.y; v.z *= w.z; v.w *= w.w;
        msg4[idx] = v;
    }
    __syncthreads();

    const float4* m4 = (const float4*)msg;
    for (int idx = tid; idx < 19*96; idx += 256) {
        float4 acc = make_float4(0.f,0.f,0.f,0.f);
        int j = idx / 96, c4 = idx - j*96;
        #pragma unroll
        for (int n = 0; n < 25; n++) {
            float w = wp[j*25 + n];
            float4 m = m4[n*96 + c4];
            acc.x += w*m.x; acc.y += w*m.y; acc.z += w*m.z; acc.w += w*m.w;
        }
        long base = (long)e*MP_STRIDE + (long)idx*4;
        __nv_bfloat16 h0 = __float2bfloat16(acc.x);
        __nv_bfloat16 h1 = __float2bfloat16(acc.y);
        __nv_bfloat16 h2 = __float2bfloat16(acc.z);
        __nv_bfloat16 h3 = __float2bfloat16(acc.w);
        __nv_bfloat162 hp0; hp0.x = h0; hp0.y = h1;
        __nv_bfloat162 hp1; hp1.x = h2; hp1.y = h3;
        ((__nv_bfloat162*)(g_mp_hi + base))[0] = hp0;
        ((__nv_bfloat162*)(g_mp_hi + base))[1] = hp1;
        __nv_bfloat162 lp0, lp1;
        lp0.x = __float2bfloat16(acc.x - __bfloat162float(h0));
        lp0.y = __float2bfloat16(acc.y - __bfloat162float(h1));
        lp1.x = __float2bfloat16(acc.z - __bfloat162float(h2));
        lp1.y = __float2bfloat16(acc.w - __bfloat162float(h3));
        ((__nv_bfloat162*)(g_mp_lo + base))[0] = lp0;
        ((__nv_bfloat162*)(g_mp_lo + base))[1] = lp1;
    }
}

// ---------------- K3 (merged): mma.sync bf16x3 GEMM, all 3 modes in one grid ----------------
// blocks: [0,711) mode0 (9 x 79), [711,1339) mode1 (4 x 157), [1339,1810) mode2 (3 x 157)
#define K3_ROWB   80
#define K3_STG    40960
#define K3_DSMEM  (2*K3_STG)   // 81920
#define K3_GRID   1810

__launch_bounds__(256, 2)
__global__ void k3_all(const float* __restrict__ bias) {
    int id = blockIdx.x;
    int mode, nbx, mby;
    if (id < 711)       { mode = 0; nbx = id % 9;            mby = id / 9; }
    else if (id < 1339) { int t = id - 711;  mode = 1; nbx = t & 3; mby = t >> 2; }
    else                { int t = id - 1339; mode = 2; nbx = t % 3; mby = t / 3; }

    const int N  = (mode==0) ? 1088 : (mode==1) ? 512 : 384;
    const int K  = (mode==0) ? 1920 : (mode==1) ? 1536 : 1152;
    const int M  = (mode==0) ? E_EDGES : 2*E_EDGES;
    const int KC = K >> 5;
    const __nv_bfloat16* __restrict__ Whi = (mode==0) ? g_wm0_hi : (mode==1) ? g_wm1_hi : g_wm2_hi;
    const __nv_bfloat16* __restrict__ Wlo = (mode==0) ? g_wm0_lo : (mode==1) ? g_wm1_lo : g_wm2_lo;
    float* __restrict__ C = (mode==0) ? g_x0 : (mode==1) ? g_ym1 : g_ym2;

    extern __shared__ char dsm[];
    const uint32_t smb = smem_u32(dsm);
    const int tid = threadIdx.x;
    const int wid = tid >> 5, lane = tid & 31;
    const int n0 = nbx * 128;
    const int m0 = mby * 128;
    const int wm = (wid & 1) * 64;
    const int wn = (wid >> 1) * 32;

    float acc[4][4][4];
    #pragma unroll
    for (int i = 0; i < 4; i++)
        #pragma unroll
        for (int j = 0; j < 4; j++)
            #pragma unroll
            for (int q = 0; q < 4; q++) acc[i][j][q] = 0.f;

    const int lr = tid >> 2, slot = tid & 3;
    const __nv_bfloat16* aP[2];
    const __nv_bfloat16* wP[2];
    #pragma unroll
    for (int j = 0; j < 2; j++) {
        int r = lr + 64*j;
        int gr = m0 + r; if (gr >= M) gr = 0;
        long ab;
        if (mode == 0)      ab = (long)gr*MP_STRIDE;
        else if (mode == 1) ab = (long)(gr>>1)*MP_STRIDE + 1920 + (long)(gr&1)*1536;
        else                ab = (long)(gr>>1)*MP_STRIDE + 4992 + (long)(gr&1)*1152;
        aP[j] = g_mp_hi + ab + slot*8;
        int gn = n0 + r; if (gn >= N) gn = N-1;
        wP[j] = Whi + (long)gn*K + slot*8;
    }
    const long adel = (const __nv_bfloat16*)g_mp_lo - (const __nv_bfloat16*)g_mp_hi;
    const long wdel = Wlo - Whi;

    auto issue = [&](int c) {
        if (c < KC) {
            int k0 = c * 32;
            uint32_t st = smb + (c & 1) * K3_STG;
            #pragma unroll
            for (int j = 0; j < 2; j++) {
                uint32_t d = st + (lr + 64*j)*K3_ROWB + slot*16;
                cp16(d,         aP[j] + k0);
                cp16(d + 10240, aP[j] + adel + k0);
                cp16(d + 20480, wP[j] + k0);
                cp16(d + 30720, wP[j] + wdel + k0);
            }
        }
        asm volatile("cp.async.commit_group;" ::: "memory");
    };

    issue(0); issue(1);

    const int a_row = lane & 15, a_kh = lane >> 4;
    const int b_nl  = (lane & 7) | ((lane >> 4) << 3);
    const int b_kh  = (lane >> 3) & 1;

    for (int c = 0; c < KC; c++) {
        uint32_t st = smb + (c & 1) * K3_STG;
        asm volatile("cp.async.wait_group 1;" ::: "memory");
        __syncthreads();
        uint32_t aH = st +         (wm + a_row)*K3_ROWB + a_kh*16;
        uint32_t bH = st + 20480 + (wn + b_nl)*K3_ROWB + b_kh*16;
        #pragma unroll
        for (int ks = 0; ks < 2; ks++) {
            uint32_t af[4][4], bf[2][4], tb[2][4];
            #pragma unroll
            for (int mi = 0; mi < 4; mi++) ldm_x4(aH + ks*32 + mi*16*K3_ROWB, af[mi]);
            #pragma unroll
            for (int nf = 0; nf < 2; nf++) ldm_x4(bH + ks*32 + nf*16*K3_ROWB, bf[nf]);
            #pragma unroll
            for (int mi = 0; mi < 4; mi++)
                #pragma unroll
                for (int ni = 0; ni < 4; ni++)
                    mma16816(acc[mi][ni], af[mi], bf[ni>>1][(ni&1)*2], bf[ni>>1][(ni&1)*2+1]);
            #pragma unroll
            for (int nf = 0; nf < 2; nf++) ldm_x4(bH + 10240 + ks*32 + nf*16*K3_ROWB, tb[nf]);
            #pragma unroll
            for (int mi = 0; mi < 4; mi++)
                #pragma unroll
                for (int ni = 0; ni < 4; ni++)
                    mma16816(acc[mi][ni], af[mi], tb[ni>>1][(ni&1)*2], tb[ni>>1][(ni&1)*2+1]);
            #pragma unroll
            for (int mi = 0; mi < 4; mi++) ldm_x4(aH + 10240 + ks*32 + mi*16*K3_ROWB, af[mi]);
            #pragma unroll
            for (int mi = 0; mi < 4; mi++)
                #pragma unroll
                for (int ni = 0; ni < 4; ni++)
                    mma16816(acc[mi][ni], af[mi], bf[ni>>1][(ni&1)*2], bf[ni>>1][(ni&1)*2+1]);
        }
        __syncthreads();
        issue(c + 2);
    }

    int tg = lane >> 2, tig = lane & 3;
    #pragma unroll
    for (int mi = 0; mi < 4; mi++) {
        #pragma unroll
        for (int ni = 0; ni < 4; ni++) {
            int row = m0 + wm + 16*mi + tg;
            int col = n0 + wn + 8*ni + 2*tig;
            if (col < N) {
                float bx = 0.f, by = 0.f;
                if (mode == 0) { float2 bb = *(const float2*)(bias + col); bx = bb.x; by = bb.y; }
                if (row < M) {
                    float2 v = make_float2(acc[mi][ni][0] + bx, acc[mi][ni][1] + by);
                    *(float2*)(C + (long)row*N + col) = v;
                }
                if (row + 8 < M) {
                    float2 v = make_float2(acc[mi][ni][2] + bx, acc[mi][ni][3] + by);
                    *(float2*)(C + (long)(row+8)*N + col) = v;
                }
            }
        }
    }
}

// ---------------- K5: recombine+gate + Wigner back + projection (4 edges/block) ----------------
// dynamic smem: s_w 4*475 | s_hl 4*1216 | s_full 4*1600 | s_pw 128*65
#define K5_DSMEM ((1900 + 4864 + 6400 + 8320)*4)   // 85936

__launch_bounds__(256)
__global__ void k5_out(const float* __restrict__ wig,
                       const float* __restrict__ pw, const float* __restrict__ pb,
                       float* __restrict__ out) {
    extern __shared__ float sm[];
    float* s_w    = sm;           // 1900
    float* s_hl   = sm + 1900;    // 4864
    float* s_full = sm + 6764;    // 6400
    float* s_pw   = sm + 13164;   // 8320
    int e0 = blockIdx.x * 4;
    int tid = threadIdx.x;

    for (int idx = tid; idx < 1900; idx += 256) {
        int e = idx / 475, rem = idx - e*475;
        int r = rem / 25, n = rem - r*25;
        s_w[idx] = wig[(long)(e0+e)*625 + c_MASK[r]*25 + n];
    }
    // fused recombine + gating + inverse perm
    for (int idx = tid; idx < 4864; idx += 256) {
        int e = idx / 1216, rem = idx - e*1216;
        int j = rem >> 6, i = rem & 63;
        const float* x0 = g_x0  + (long)(e0+e)*X0_DIM;
        const float* y1 = g_ym1 + (long)(e0+e)*1024;
        const float* y2 = g_ym2 + (long)(e0+e)*768;
        float val;
        if (j < 5)        val = x0[768 + (j<<6) + i];
        else if (j < 9)  { int jj = j-5;  val = y1[jj*64 + i]       - y1[768 + jj*64 + i]; }
        else if (j < 13) { int jj = j-9;  val = y1[512 + jj*64 + i] + y1[256 + jj*64 + i]; }
        else if (j < 16) { int jj = j-13; val = y2[jj*64 + i]       - y2[576 + jj*64 + i]; }
        else             { int jj = j-16; val = y2[384 + jj*64 + i] + y2[192 + jj*64 + i]; }
        if (j == 0) {
            val = val * sigm(val);
        } else {
            float gsrc = x0[512 + (c_LPERM[j]-1)*64 + i];
            val *= sigm(gsrc);
        }
        s_hl[e*1216 + c_PERM[j]*64 + i] = val;
    }
    __syncthreads();
    for (int idx = tid; idx < 6400; idx += 256) {
        int e = idx / 1600, rem = idx - e*1600;
        int n = rem >> 6, i = rem & 63;
        float acc = 0.f;
        #pragma unroll
        for (int r = 0; r < 19; r++)
            acc += s_w[e*475 + r*25 + n] * s_hl[e*1216 + r*64 + i];
        s_full[idx] = acc;
    }

    int o = tid & 127, ph = tid >> 7;
    for (int l = 0; l < 5; l++) {
        __syncthreads();
        for (int idx = tid; idx < 8192; idx += 256)
            s_pw[(idx >> 6)*65 + (idx & 63)] = pw[l*8192 + idx];
        __syncthreads();
        int nrows = 2*l + 1, nstart = l*l;
        int npairs = 4*nrows;
        const float* pwrow = &s_pw[o*65];
        for (int p = ph; p < npairs; p += 2) {
            int e = p & 3, nr = p >> 2;
            const float* fu = &s_full[(e*25 + nstart + nr)*64];
            float acc = 0.f;
            #pragma unroll
            for (int i0 = 0; i0 < 64; i0 += 4) {
                float4 f = *(const float4*)(fu + i0);
                acc += f.x*pwrow[i0] + f.y*pwrow[i0+1] + f.z*pwrow[i0+2] + f.w*pwrow[i0+3];
            }
            if (l == 0) acc += pb[o];
            out[(long)(e0+e)*3200 + (nstart+nr)*128 + o] = acc;
        }
    }
}

// ---------------- launch ----------------
extern "C" void kernel_launch(void* const* d_in, const int* in_sizes, int n_in,
                              void* d_out, int out_size) {
    const float* x    = (const float*)d_in[0];
    const float* ef   = (const float*)d_in[1];
    const float* ed   = (const float*)d_in[2];
    const float* wig  = (const float*)d_in[3];
    const float* semb = (const float*)d_in[4];
    const float* temb = (const float*)d_in[5];
    const float* w1   = (const float*)d_in[6];
    const float* b1   = (const float*)d_in[7];
    const float* g1   = (const float*)d_in[8];
    const float* bb1  = (const float*)d_in[9];
    const float* w2   = (const float*)d_in[10];
    const float* b2   = (const float*)d_in[11];
    const float* g2   = (const float*)d_in[12];
    const float* bb2  = (const float*)d_in[13];
    const float* w3   = (const float*)d_in[14];
    const float* b3   = (const float*)d_in[15];
    const float* wm0  = (const float*)d_in[16];
    const float* bm0  = (const float*)d_in[17];
    const float* wm1  = (const float*)d_in[18];
    const float* wm2  = (const float*)d_in[19];
    const float* pw   = (const float*)d_in[20];
    const float* pb   = (const float*)d_in[21];
    const int*   an   = (const int*)d_in[22];
    const int*   ei   = (const int*)d_in[23];
    float* out = (float*)d_out;

    static bool attr_done = false;
    if (!attr_done) {
        cudaFuncSetAttribute(k3_all, cudaFuncAttributeMaxDynamicSharedMemorySize, K3_DSMEM);
        cudaFuncSetAttribute(k5_out, cudaFuncAttributeMaxDynamicSharedMemorySize, K5_DSMEM);
        attr_done = true;
    }

    // launch 0: fused prelude
    k0_fused<<<14176, 256>>>(w1, w2, w3, wm0, wm1, wm2);

    // launch 1: radial MLP
    k1_radial<<<E_EDGES/16, 256>>>(ed, semb, temb, b1, g1, bb1, b2, g2, bb2, b3, an, ei);

    // launch 2: msg * w_rad + Wigner forward
    k2_wfwd<<<E_EDGES, 256>>>(x, ef, wig, ei);

    // launch 3 (profiled): merged tensor-core GEMMs
    k3_all<<<K3_GRID, 256, K3_DSMEM>>>(bm0);

    // launch 4: fused recombine + Wigner back + projection (4 edges/block)
    k5_out<<<E_EDGES/4, 256, K5_DSMEM>>>(wig, pw, pb, out);
}

// round 8
// speedup vs baseline: 1.8305x; 1.0001x over previous
#include <cuda_runtime.h>
#include <cuda_bf16.h>
#include <cstdint>

// ---------------- problem constants ----------------
#define E_EDGES   10000
#define NRED      19
#define MP_STRIDE (NRED*384)   // 7296
#define X0_DIM    1088

// ---------------- scratch (__device__ globals) ----------------
__device__ float g_w1T [384*128];
__device__ float g_w2T [128*128];
__device__ float g_w3T [128*1920];
__device__ __nv_bfloat16 g_wm0_hi[1088*1920];
__device__ __nv_bfloat16 g_wm0_lo[1088*1920];
__device__ __nv_bfloat16 g_wm1_hi[512*1536];
__device__ __nv_bfloat16 g_wm1_lo[512*1536];
__device__ __nv_bfloat16 g_wm2_hi[384*1152];
__device__ __nv_bfloat16 g_wm2_lo[384*1152];
__device__ float g_wrad[(long)E_EDGES*1920];
__device__ __nv_bfloat16 g_mp_hi[(long)E_EDGES*MP_STRIDE];
__device__ __nv_bfloat16 g_mp_lo[(long)E_EDGES*MP_STRIDE];
__device__ float g_x0  [(long)E_EDGES*X0_DIM];
__device__ float g_ym1 [(long)E_EDGES*2*512];
__device__ float g_ym2 [(long)E_EDGES*2*384];

// permutation tables
__constant__ int c_MASKP[19] = {0,2,6,12,20, 3,7,13,21, 1,5,11,19, 8,14,22, 4,10,18};
__constant__ int c_MASK [19] = {0,1,2,3,4,5,6,7,8,10,11,12,13,14,18,19,20,21,22};
__constant__ int c_PERM [19] = {0,2,6,11,16, 3,7,12,17, 1,5,10,15, 8,13,18, 4,9,14};
__constant__ int c_LPERM[19] = {0,1,2,3,4, 1,2,3,4, 1,2,3,4, 2,3,4, 2,3,4};
__constant__ int c_LFULL[25] = {0,1,1,1,2,2,2,2,2,3,3,3,3,3,3,3,4,4,4,4,4,4,4,4,4};

__device__ __forceinline__ float sigm(float x){ return 1.f/(1.f+__expf(-x)); }

__device__ __forceinline__ uint32_t smem_u32(const void* p) {
    uint32_t a;
    asm("{ .reg .u64 t; cvta.to.shared.u64 t, %1; cvt.u32.u64 %0, t; }" : "=r"(a) : "l"(p));
    return a;
}
__device__ __forceinline__ void cp16(uint32_t dst, const void* src) {
    asm volatile("cp.async.cg.shared.global [%0], [%1], 16;" :: "r"(dst), "l"(src));
}
__device__ __forceinline__ void ldm_x4(uint32_t addr, uint32_t* r) {
    asm volatile("ldmatrix.sync.aligned.m8n8.x4.shared.b16 {%0,%1,%2,%3}, [%4];"
                 : "=r"(r[0]), "=r"(r[1]), "=r"(r[2]), "=r"(r[3]) : "r"(addr));
}
__device__ __forceinline__ void mma16816(float* d, const uint32_t* a, uint32_t b0, uint32_t b1) {
    asm volatile("mma.sync.aligned.m16n8k16.row.col.f32.bf16.bf16.f32 "
                 "{%0,%1,%2,%3}, {%4,%5,%6,%7}, {%8,%9}, {%0,%1,%2,%3};"
                 : "+f"(d[0]), "+f"(d[1]), "+f"(d[2]), "+f"(d[3])
                 : "r"(a[0]), "r"(a[1]), "r"(a[2]), "r"(a[3]), "r"(b0), "r"(b1));
}

// ---------------- K0 (fused): transposes + bf16 splits, single launch ----------------
__global__ void k0_fused(const float* __restrict__ w1, const float* __restrict__ w2,
                         const float* __restrict__ w3, const float* __restrict__ wm0,
                         const float* __restrict__ wm1, const float* __restrict__ wm2) {
    long i = (long)blockIdx.x*256 + threadIdx.x;
    if (i < 49152) { int r = (int)(i/384), c = (int)(i%384); g_w1T[c*128+r] = w1[i]; return; }
    i -= 49152;
    if (i < 16384) { int r = (int)(i/128), c = (int)(i%128); g_w2T[c*128+r] = w2[i]; return; }
    i -= 16384;
    if (i < 245760) { int r = (int)(i/128), c = (int)(i%128); g_w3T[c*1920+r] = w3[i]; return; }
    i -= 245760;
    if (i < 2088960) {
        float v = wm0[i]; __nv_bfloat16 h = __float2bfloat16(v);
        g_wm0_hi[i] = h; g_wm0_lo[i] = __float2bfloat16(v - __bfloat162float(h));
        return;
    }
    i -= 2088960;
    if (i < 786432) {
        float v = wm1[i]; __nv_bfloat16 h = __float2bfloat16(v);
        g_wm1_hi[i] = h; g_wm1_lo[i] = __float2bfloat16(v - __bfloat162float(h));
        return;
    }
    i -= 786432;
    if (i < 442368) {
        float v = wm2[i]; __nv_bfloat16 h = __float2bfloat16(v);
        g_wm2_hi[i] = h; g_wm2_lo[i] = __float2bfloat16(v - __bfloat162float(h));
    }
}

// ---------------- K1: radial MLP (16 edges/block) ----------------
__device__ __forceinline__ void ln_silu16(float* buf, const float* __restrict__ g, const float* __restrict__ b) {
    int tid = threadIdx.x, w = tid >> 5, lane = tid & 31;
    for (int le = w; le < 16; le += 8) {
        float s = 0.f, s2 = 0.f;
        #pragma unroll
        for (int q = 0; q < 4; q++) { float v = buf[le*128 + lane + 32*q]; s += v; s2 += v*v; }
        #pragma unroll
        for (int off = 16; off > 0; off >>= 1) {
            s  += __shfl_xor_sync(0xffffffffu, s,  off);
            s2 += __shfl_xor_sync(0xffffffffu, s2, off);
        }
        float mu = s * (1.f/128.f);
        float var = s2 * (1.f/128.f) - mu*mu;
        float rstd = rsqrtf(var + 1e-5f);
        #pragma unroll
        for (int q = 0; q < 4; q++) {
            int oo = lane + 32*q;
            float v = buf[le*128 + oo];
            v = (v - mu)*rstd*g[oo] + b[oo];
            buf[le*128 + oo] = v * sigm(v);
        }
    }
}

__launch_bounds__(256)
__global__ void k1_radial(const float* __restrict__ ed,
                          const float* __restrict__ semb, const float* __restrict__ temb,
                          const float* __restrict__ b1, const float* __restrict__ g1, const float* __restrict__ bb1,
                          const float* __restrict__ b2, const float* __restrict__ g2, const float* __restrict__ bb2,
                          const float* __restrict__ b3,
                          const int* __restrict__ an, const int* __restrict__ ei) {
    __shared__ float xe[16*384];
    __shared__ float h1[16*128];
    __shared__ float h2[16*128];
    int e0 = blockIdx.x * 16;
    int tid = threadIdx.x;

    for (int idx = tid; idx < 16*384; idx += 256) {
        int le = idx / 384, c = idx - le*384;
        int e = e0 + le;
        float v;
        if (c < 128)       v = ed[e*128 + c];
        else if (c < 256)  v = semb[an[ei[e]]*128 + (c-128)];
        else               v = temb[an[ei[E_EDGES + e]]*128 + (c-256)];
        xe[idx] = v;
    }
    __syncthreads();

    int o = tid & 127, hh = tid >> 7;
    {
        float acc[8]; float bv = b1[o];
        #pragma unroll
        for (int j = 0; j < 8; j++) acc[j] = bv;
        #pragma unroll 4
        for (int k = 0; k < 384; k++) {
            float wv = g_w1T[k*128 + o];
            #pragma unroll
            for (int j = 0; j < 8; j++) acc[j] += wv * xe[(hh*8+j)*384 + k];
        }
        #pragma unroll
        for (int j = 0; j < 8; j++) h1[(hh*8+j)*128 + o] = acc[j];
    }
    __syncthreads();
    ln_silu16(h1, g1, bb1);
    __syncthreads();
    {
        float acc[8]; float bv = b2[o];
        #pragma unroll
        for (int j = 0; j < 8; j++) acc[j] = bv;
        #pragma unroll 4
        for (int k = 0; k < 128; k++) {
            float wv = g_w2T[k*128 + o];
            #pragma unroll
            for (int j = 0; j < 8; j++) acc[j] += wv * h1[(hh*8+j)*128 + k];
        }
        #pragma unroll
        for (int j = 0; j < 8; j++) h2[(hh*8+j)*128 + o] = acc[j];
    }
    __syncthreads();
    ln_silu16(h2, g2, bb2);
    __syncthreads();
    for (int oo = tid; oo < 1920; oo += 256) {
        float acc[16];
        #pragma unroll
        for (int le = 0; le < 16; le++) acc[le] = 0.f;
        #pragma unroll 4
        for (int k = 0; k < 128; k++) {
            float wv = g_w3T[k*1920 + oo];
            #pragma unroll
            for (int le = 0; le < 16; le++) acc[le] += wv * h2[le*128 + k];
        }
        float bv = b3[oo];
        #pragma unroll
        for (int le = 0; le < 16; le++)
            g_wrad[(long)(e0+le)*1920 + oo] = acc[le] + bv;
    }
}

// ---------------- K2: msg build * w_rad, Wigner fwd, permuted bf16-split store ----------------
__launch_bounds__(256)
__global__ void k2_wfwd(const float* __restrict__ x, const float* __restrict__ ef,
                        const float* __restrict__ wig, const int* __restrict__ ei) {
    __shared__ float msg[25*384];
    __shared__ float wp[19*25];
    int e = blockIdx.x, tid = threadIdx.x;
    int src = ei[e], tgt = ei[E_EDGES + e];

    for (int idx = tid; idx < 475; idx += 256) {
        int j = idx / 25, n = idx - j*25;
        wp[idx] = wig[(long)e*625 + c_MASKP[j]*25 + n];
    }
    const float4* x4  = (const float4*)x;
    const float4* ef4 = (const float4*)ef;
    const float4* wr4 = (const float4*)(g_wrad + (long)e*1920);
    float4* msg4 = (float4*)msg;
    for (int idx = tid; idx < 25*96; idx += 256) {
        int n = idx / 96, c4 = idx - n*96;
        float4 v;
        if (c4 < 32)      v = x4[(long)src*800 + n*32 + c4];
        else if (c4 < 64) v = x4[(long)tgt*800 + n*32 + (c4-32)];
        else              v = ef4[(long)e*800 + n*32 + (c4-64)];
        float4 w = wr4[c_LFULL[n]*96 + c4];
        v.x *= w.x; v.y *= w.y; v.z *= w.z; v.w *= w.w;
        msg4[idx] = v;
    }
    __syncthreads();

    const float4* m4 = (const float4*)msg;
    for (int idx = tid; idx < 19*96; idx += 256) {
        float4 acc = make_float4(0.f,0.f,0.f,0.f);
        int j = idx / 96, c4 = idx - j*96;
        #pragma unroll
        for (int n = 0; n < 25; n++) {
            float w = wp[j*25 + n];
            float4 m = m4[n*96 + c4];
            acc.x += w*m.x; acc.y += w*m.y; acc.z += w*m.z; acc.w += w*m.w;
        }
        long base = (long)e*MP_STRIDE + (long)idx*4;
        __nv_bfloat16 h0 = __float2bfloat16(acc.x);
        __nv_bfloat16 h1 = __float2bfloat16(acc.y);
        __nv_bfloat16 h2 = __float2bfloat16(acc.z);
        __nv_bfloat16 h3 = __float2bfloat16(acc.w);
        __nv_bfloat162 hp0; hp0.x = h0; hp0.y = h1;
        __nv_bfloat162 hp1; hp1.x = h2; hp1.y = h3;
        ((__nv_bfloat162*)(g_mp_hi + base))[0] = hp0;
        ((__nv_bfloat162*)(g_mp_hi + base))[1] = hp1;
        __nv_bfloat162 lp0, lp1;
        lp0.x = __float2bfloat16(acc.x - __bfloat162float(h0));
        lp0.y = __float2bfloat16(acc.y - __bfloat162float(h1));
        lp1.x = __float2bfloat16(acc.z - __bfloat162float(h2));
        lp1.y = __float2bfloat16(acc.w - __bfloat162float(h3));
        ((__nv_bfloat162*)(g_mp_lo + base))[0] = lp0;
        ((__nv_bfloat162*)(g_mp_lo + base))[1] = lp1;
    }
}

// ---------------- K3 (merged): mma.sync bf16x3 GEMM, all 3 modes in one grid ----------------
// blocks: [0,711) mode0 (9 x 79), [711,1339) mode1 (4 x 157), [1339,1810) mode2 (3 x 157)
#define K3_ROWB   80
#define K3_STG    40960
#define K3_DSMEM  (2*K3_STG)   // 81920
#define K3_GRID   1810

__launch_bounds__(256, 2)
__global__ void k3_all(const float* __restrict__ bias) {
    int id = blockIdx.x;
    int mode, nbx, mby;
    if (id < 711)       { mode = 0; nbx = id % 9;            mby = id / 9; }
    else if (id < 1339) { int t = id - 711;  mode = 1; nbx = t & 3; mby = t >> 2; }
    else                { int t = id - 1339; mode = 2; nbx = t % 3; mby = t / 3; }

    const int N  = (mode==0) ? 1088 : (mode==1) ? 512 : 384;
    const int K  = (mode==0) ? 1920 : (mode==1) ? 1536 : 1152;
    const int M  = (mode==0) ? E_EDGES : 2*E_EDGES;
    const int KC = K >> 5;
    const __nv_bfloat16* __restrict__ Whi = (mode==0) ? g_wm0_hi : (mode==1) ? g_wm1_hi : g_wm2_hi;
    const __nv_bfloat16* __restrict__ Wlo = (mode==0) ? g_wm0_lo : (mode==1) ? g_wm1_lo : g_wm2_lo;
    float* __restrict__ C = (mode==0) ? g_x0 : (mode==1) ? g_ym1 : g_ym2;

    extern __shared__ char dsm[];
    const uint32_t smb = smem_u32(dsm);
    const int tid = threadIdx.x;
    const int wid = tid >> 5, lane = tid & 31;
    const int n0 = nbx * 128;
    const int m0 = mby * 128;
    const int wm = (wid & 1) * 64;
    const int wn = (wid >> 1) * 32;

    float acc[4][4][4];
    #pragma unroll
    for (int i = 0; i < 4; i++)
        #pragma unroll
        for (int j = 0; j < 4; j++)
            #pragma unroll
            for (int q = 0; q < 4; q++) acc[i][j][q] = 0.f;

    const int lr = tid >> 2, slot = tid & 3;
    const __nv_bfloat16* aP[2];
    const __nv_bfloat16* wP[2];
    #pragma unroll
    for (int j = 0; j < 2; j++) {
        int r = lr + 64*j;
        int gr = m0 + r; if (gr >= M) gr = 0;
        long ab;
        if (mode == 0)      ab = (long)gr*MP_STRIDE;
        else if (mode == 1) ab = (long)(gr>>1)*MP_STRIDE + 1920 + (long)(gr&1)*1536;
        else                ab = (long)(gr>>1)*MP_STRIDE + 4992 + (long)(gr&1)*1152;
        aP[j] = g_mp_hi + ab + slot*8;
        int gn = n0 + r; if (gn >= N) gn = N-1;
        wP[j] = Whi + (long)gn*K + slot*8;
    }
    const long adel = (const __nv_bfloat16*)g_mp_lo - (const __nv_bfloat16*)g_mp_hi;
    const long wdel = Wlo - Whi;

    auto issue = [&](int c) {
        if (c < KC) {
            int k0 = c * 32;
            uint32_t st = smb + (c & 1) * K3_STG;
            #pragma unroll
            for (int j = 0; j < 2; j++) {
                uint32_t d = st + (lr + 64*j)*K3_ROWB + slot*16;
                cp16(d,         aP[j] + k0);
                cp16(d + 10240, aP[j] + adel + k0);
                cp16(d + 20480, wP[j] + k0);
                cp16(d + 30720, wP[j] + wdel + k0);
            }
        }
        asm volatile("cp.async.commit_group;" ::: "memory");
    };

    issue(0); issue(1);

    const int a_row = lane & 15, a_kh = lane >> 4;
    const int b_nl  = (lane & 7) | ((lane >> 4) << 3);
    const int b_kh  = (lane >> 3) & 1;

    for (int c = 0; c < KC; c++) {
        uint32_t st = smb + (c & 1) * K3_STG;
        asm volatile("cp.async.wait_group 1;" ::: "memory");
        __syncthreads();
        uint32_t aH = st +         (wm + a_row)*K3_ROWB + a_kh*16;
        uint32_t bH = st + 20480 + (wn + b_nl)*K3_ROWB + b_kh*16;
        #pragma unroll
        for (int ks = 0; ks < 2; ks++) {
            uint32_t af[4][4], bf[2][4], tb[2][4];
            #pragma unroll
            for (int mi = 0; mi < 4; mi++) ldm_x4(aH + ks*32 + mi*16*K3_ROWB, af[mi]);
            #pragma unroll
            for (int nf = 0; nf < 2; nf++) ldm_x4(bH + ks*32 + nf*16*K3_ROWB, bf[nf]);
            #pragma unroll
            for (int mi = 0; mi < 4; mi++)
                #pragma unroll
                for (int ni = 0; ni < 4; ni++)
                    mma16816(acc[mi][ni], af[mi], bf[ni>>1][(ni&1)*2], bf[ni>>1][(ni&1)*2+1]);
            #pragma unroll
            for (int nf = 0; nf < 2; nf++) ldm_x4(bH + 10240 + ks*32 + nf*16*K3_ROWB, tb[nf]);
            #pragma unroll
            for (int mi = 0; mi < 4; mi++)
                #pragma unroll
                for (int ni = 0; ni < 4; ni++)
                    mma16816(acc[mi][ni], af[mi], tb[ni>>1][(ni&1)*2], tb[ni>>1][(ni&1)*2+1]);
            #pragma unroll
            for (int mi = 0; mi < 4; mi++) ldm_x4(aH + 10240 + ks*32 + mi*16*K3_ROWB, af[mi]);
            #pragma unroll
            for (int mi = 0; mi < 4; mi++)
                #pragma unroll
                for (int ni = 0; ni < 4; ni++)
                    mma16816(acc[mi][ni], af[mi], bf[ni>>1][(ni&1)*2], bf[ni>>1][(ni&1)*2+1]);
        }
        __syncthreads();
        issue(c + 2);
    }

    int tg = lane >> 2, tig = lane & 3;
    #pragma unroll
    for (int mi = 0; mi < 4; mi++) {
        #pragma unroll
        for (int ni = 0; ni < 4; ni++) {
            int row = m0 + wm + 16*mi + tg;
            int col = n0 + wn + 8*ni + 2*tig;
            if (col < N) {
                float bx = 0.f, by = 0.f;
                if (mode == 0) { float2 bb = *(const float2*)(bias + col); bx = bb.x; by = bb.y; }
                if (row < M) {
                    float2 v = make_float2(acc[mi][ni][0] + bx, acc[mi][ni][1] + by);
                    *(float2*)(C + (long)row*N + col) = v;
                }
                if (row + 8 < M) {
                    float2 v = make_float2(acc[mi][ni][2] + bx, acc[mi][ni][3] + by);
                    *(float2*)(C + (long)(row+8)*N + col) = v;
                }
            }
        }
    }
}

// ---------------- K5: recombine+gate + Wigner back + projection (4 edges/block) ----------------
// dynamic smem: s_w 4*475 | s_hl 4*1216 | s_full 4*1600 | s_pw 128*65
#define K5_DSMEM ((1900 + 4864 + 6400 + 8320)*4)   // 85936

__launch_bounds__(256)
__global__ void k5_out(const float* __restrict__ wig,
                       const float* __restrict__ pw, const float* __restrict__ pb,
                       float* __restrict__ out) {
    extern __shared__ float sm[];
    float* s_w    = sm;           // 1900
    float* s_hl   = sm + 1900;    // 4864
    float* s_full = sm + 6764;    // 6400
    float* s_pw   = sm + 13164;   // 8320
    int e0 = blockIdx.x * 4;
    int tid = threadIdx.x;

    for (int idx = tid; idx < 1900; idx += 256) {
        int e = idx / 475, rem = idx - e*475;
        int r = rem / 25, n = rem - r*25;
        s_w[idx] = wig[(long)(e0+e)*625 + c_MASK[r]*25 + n];
    }
    // fused recombine + gating + inverse perm
    for (int idx = tid; idx < 4864; idx += 256) {
        int e = idx / 1216, rem = idx - e*1216;
        int j = rem >> 6, i = rem & 63;
        const float* x0 = g_x0  + (long)(e0+e)*X0_DIM;
        const float* y1 = g_ym1 + (long)(e0+e)*1024;
        const float* y2 = g_ym2 + (long)(e0+e)*768;
        float val;
        if (j < 5)        val = x0[768 + (j<<6) + i];
        else if (j < 9)  { int jj = j-5;  val = y1[jj*64 + i]       - y1[768 + jj*64 + i]; }
        else if (j < 13) { int jj = j-9;  val = y1[512 + jj*64 + i] + y1[256 + jj*64 + i]; }
        else if (j < 16) { int jj = j-13; val = y2[jj*64 + i]       - y2[576 + jj*64 + i]; }
        else             { int jj = j-16; val = y2[384 + jj*64 + i] + y2[192 + jj*64 + i]; }
        if (j == 0) {
            val = val * sigm(val);
        } else {
            float gsrc = x0[512 + (c_LPERM[j]-1)*64 + i];
            val *= sigm(gsrc);
        }
        s_hl[e*1216 + c_PERM[j]*64 + i] = val;
    }
    __syncthreads();
    for (int idx = tid; idx < 6400; idx += 256) {
        int e = idx / 1600, rem = idx - e*1600;
        int n = rem >> 6, i = rem & 63;
        float acc = 0.f;
        #pragma unroll
        for (int r = 0; r < 19; r++)
            acc += s_w[e*475 + r*25 + n] * s_hl[e*1216 + r*64 + i];
        s_full[idx] = acc;
    }

    int o = tid & 127, ph = tid >> 7;
    for (int l = 0; l < 5; l++) {
        __syncthreads();
        for (int idx = tid; idx < 8192; idx += 256)
            s_pw[(idx >> 6)*65 + (idx & 63)] = pw[l*8192 + idx];
        __syncthreads();
        int nrows = 2*l + 1, nstart = l*l;
        int npairs = 4*nrows;
        const float* pwrow = &s_pw[o*65];
        for (int p = ph; p < npairs; p += 2) {
            int e = p & 3, nr = p >> 2;
            const float* fu = &s_full[(e*25 + nstart + nr)*64];
            float acc = 0.f;
            #pragma unroll
            for (int i0 = 0; i0 < 64; i0 += 4) {
                float4 f = *(const float4*)(fu + i0);
                acc += f.x*pwrow[i0] + f.y*pwrow[i0+1] + f.z*pwrow[i0+2] + f.w*pwrow[i0+3];
            }
            if (l == 0) acc += pb[o];
            out[(long)(e0+e)*3200 + (nstart+nr)*128 + o] = acc;
        }
    }
}

// ---------------- launch ----------------
extern "C" void kernel_launch(void* const* d_in, const int* in_sizes, int n_in,
                              void* d_out, int out_size) {
    const float* x    = (const float*)d_in[0];
    const float* ef   = (const float*)d_in[1];
    const float* ed   = (const float*)d_in[2];
    const float* wig  = (const float*)d_in[3];
    const float* semb = (const float*)d_in[4];
    const float* temb = (const float*)d_in[5];
    const float* w1   = (const float*)d_in[6];
    const float* b1   = (const float*)d_in[7];
    const float* g1   = (const float*)d_in[8];
    const float* bb1  = (const float*)d_in[9];
    const float* w2   = (const float*)d_in[10];
    const float* b2   = (const float*)d_in[11];
    const float* g2   = (const float*)d_in[12];
    const float* bb2  = (const float*)d_in[13];
    const float* w3   = (const float*)d_in[14];
    const float* b3   = (const float*)d_in[15];
    const float* wm0  = (const float*)d_in[16];
    const float* bm0  = (const float*)d_in[17];
    const float* wm1  = (const float*)d_in[18];
    const float* wm2  = (const float*)d_in[19];
    const float* pw   = (const float*)d_in[20];
    const float* pb   = (const float*)d_in[21];
    const int*   an   = (const int*)d_in[22];
    const int*   ei   = (const int*)d_in[23];
    float* out = (float*)d_out;

    static bool attr_done = false;
    if (!attr_done) {
        cudaFuncSetAttribute(k3_all, cudaFuncAttributeMaxDynamicSharedMemorySize, K3_DSMEM);
        cudaFuncSetAttribute(k5_out, cudaFuncAttributeMaxDynamicSharedMemorySize, K5_DSMEM);
        attr_done = true;
    }

    // launch 0: fused prelude
    k0_fused<<<14176, 256>>>(w1, w2, w3, wm0, wm1, wm2);

    // launch 1: radial MLP
    k1_radial<<<E_EDGES/16, 256>>>(ed, semb, temb, b1, g1, bb1, b2, g2, bb2, b3, an, ei);

    // launch 2: msg * w_rad + Wigner forward
    k2_wfwd<<<E_EDGES, 256>>>(x, ef, wig, ei);

    // launch 3 (profiled): merged tensor-core GEMMs
    k3_all<<<K3_GRID, 256, K3_DSMEM>>>(bm0);

    // launch 4: fused recombine + Wigner back + projection (4 edges/block)
    k5_out<<<E_EDGES/4, 256, K5_DSMEM>>>(wig, pw, pb, out);
}